// round 10
// baseline (speedup 1.0000x reference)
#include <cuda_runtime.h>

// ---------------------------------------------------------------------------
// Problem dims
// ---------------------------------------------------------------------------
#define DT 64      // decode steps
#define DB 64      // batch
#define DS 100     // src len
#define DH 512     // hidden
#define DE 512     // enc dim
#define DW 512     // word vec
#define G3 1536    // 3*H

// output layout offsets (float elements)
static const size_t OFF_G  = 0;                                  // (T,B,256)
static const size_t OFF_C  = OFF_G  + (size_t)DT*DB*256;         // (T,B,S)
static const size_t OFF_CP = OFF_C  + (size_t)DT*DB*DS;          // (T,B,1)
static const size_t OFF_HF = OFF_CP + (size_t)DT*DB;             // (2,B,H)
static const size_t OFF_CL = OFF_HF + (size_t)2*DB*DH;           // (B,S)
static const size_t OFF_CF = OFF_CL + (size_t)DB*DS;             // (B,E)
static const size_t OFF_GH = OFF_CF + (size_t)DB*DE;             // (T,2,B,H)

// ---------------------------------------------------------------------------
// Device scratch (no allocations allowed -> __device__ globals)
// ---------------------------------------------------------------------------
__device__ float g_emb   [(size_t)DT*DB*DW];     // gathered embeddings
__device__ float g_gi0e  [(size_t)DT*DB*G3];     // emb @ W_ih0[:, :512]^T + b_ih0
__device__ float g_re    [(size_t)DT*DB*DH];     // emb @ W_read[:, :512]^T + b_read
__device__ float g_pre   [(size_t)DB*DS*DE];     // linear_pre(context) (B,S,A)
__device__ float g_ctxbse[(size_t)DB*DS*DE];     // context transposed (B,S,E)
__device__ float g_h0    [(size_t)DB*DH];        // layer-0 hidden
__device__ float g_hc    [(size_t)DB*2*DH];      // [h1 | ctx] per batch row
__device__ float g_part  [(size_t)8*DB*G3];      // GRU gemm partials (2 mats x 4 K-splits)
__device__ float g_qp    [(size_t)4*DB*DH];      // q partials
__device__ float g_rop   [(size_t)4*DB*DH];      // readout partials

// ---------------------------------------------------------------------------
// fast math helpers (~1e-6 rel accuracy)
// ---------------------------------------------------------------------------
__device__ __forceinline__ float fex2(float x){ float y; asm("ex2.approx.f32 %0, %1;" : "=f"(y) : "f"(x)); return y; }
__device__ __forceinline__ float frcp(float x){ float y; asm("rcp.approx.f32 %0, %1;" : "=f"(y) : "f"(x)); return y; }
#define L2E 1.4426950408889634f

__device__ __forceinline__ float tanh_f(float x){
    float xc = fminf(fmaxf(x, -15.f), 15.f);
    float t  = fex2(xc * (2.f * L2E));          // e^{2x}
    return (t - 1.f) * frcp(t + 1.f);
}
__device__ __forceinline__ float sig_f(float x){
    float xc = fminf(fmaxf(x, -30.f), 30.f);
    return frcp(1.f + fex2(-xc * L2E));
}

// ---------------------------------------------------------------------------
// Generic fp32 GEMM: C[m,n] = sum_k A[m,k]*W[n,k] (+Cinit[m,n]) (+bias[n])
// block tile 64(M) x 32(N), BK=16, 128 threads, thread tile 4x4.
// up to 8 independent ops selected by blockIdx.z.
// ---------------------------------------------------------------------------
struct GOp {
    const float* A; const float* W; const float* Ci; const float* bias;
    float* C;
    int lda, ldw, ldci, ldc, K;
};
struct GOps { GOp op[8]; };

__global__ void __launch_bounds__(128) gemm_k(GOps ops) {
    GOp op = ops.op[blockIdx.z];
    __shared__ __align__(16) float As[16][64];
    __shared__ __align__(16) float Ws[16][32];
    int tid = threadIdx.x;
    int tx = tid & 15;          // m group
    int ty = tid >> 4;          // n group (0..7)
    int m0 = blockIdx.y << 6;
    int n0 = blockIdx.x << 5;

    int arow = tid >> 1, akh = (tid & 1) << 3;
    const float* Ap = op.A + (size_t)(m0 + arow) * op.lda + akh;
    int wrow = (tid & 63) >> 1, wkh = (tid & 1) << 3;
    const float* Wp = op.W + (size_t)(n0 + wrow) * op.ldw + wkh;
    bool wload = (tid < 64);

    float acc[16];
#pragma unroll
    for (int i = 0; i < 16; i++) acc[i] = 0.f;

    for (int k0 = 0; k0 < op.K; k0 += 16) {
        float4 a0 = *(const float4*)(Ap + k0);
        float4 a1 = *(const float4*)(Ap + k0 + 4);
        As[akh+0][arow] = a0.x; As[akh+1][arow] = a0.y;
        As[akh+2][arow] = a0.z; As[akh+3][arow] = a0.w;
        As[akh+4][arow] = a1.x; As[akh+5][arow] = a1.y;
        As[akh+6][arow] = a1.z; As[akh+7][arow] = a1.w;
        if (wload) {
            float4 w0 = *(const float4*)(Wp + k0);
            float4 w1 = *(const float4*)(Wp + k0 + 4);
            Ws[wkh+0][wrow] = w0.x; Ws[wkh+1][wrow] = w0.y;
            Ws[wkh+2][wrow] = w0.z; Ws[wkh+3][wrow] = w0.w;
            Ws[wkh+4][wrow] = w1.x; Ws[wkh+5][wrow] = w1.y;
            Ws[wkh+6][wrow] = w1.z; Ws[wkh+7][wrow] = w1.w;
        }
        __syncthreads();
#pragma unroll
        for (int k = 0; k < 16; k++) {
            float4 av = *(const float4*)&As[k][tx << 2];
            float4 wv = *(const float4*)&Ws[k][ty << 2];
            float a[4] = {av.x, av.y, av.z, av.w};
            float w[4] = {wv.x, wv.y, wv.z, wv.w};
#pragma unroll
            for (int i = 0; i < 4; i++)
#pragma unroll
                for (int j = 0; j < 4; j++)
                    acc[i*4+j] += a[i] * w[j];
        }
        __syncthreads();
    }

    int nb = n0 + (ty << 2);
#pragma unroll
    for (int i = 0; i < 4; i++) {
        int m = m0 + (tx << 2) + i;
        float v[4];
#pragma unroll
        for (int j = 0; j < 4; j++) {
            float c = acc[i*4+j];
            if (op.Ci)   c += op.Ci[(size_t)m * op.ldci + nb + j];
            if (op.bias) c += op.bias[nb + j];
            v[j] = c;
        }
        float4 o = {v[0], v[1], v[2], v[3]};
        *(float4*)&op.C[(size_t)m * op.ldc + nb] = o;
    }
}

// ---------------------------------------------------------------------------
// misc kernels
// ---------------------------------------------------------------------------
__global__ void gather_emb_k(const int* __restrict__ inp, const float* __restrict__ tab) {
    int tb = blockIdx.x;                 // T*B
    int idx = inp[tb];
    const float4* src = (const float4*)(tab + (size_t)idx * DW);
    float4* dst = (float4*)(g_emb + (size_t)tb * DW);
    dst[threadIdx.x] = src[threadIdx.x]; // 128 threads x float4 = 512 floats
}

__global__ void transpose_ctx_k(const float* __restrict__ ctx) {
    int s = blockIdx.x, b = blockIdx.y;
    float4 v = ((const float4*)(ctx + ((size_t)s * DB + b) * DE))[threadIdx.x];
    ((float4*)(g_ctxbse + ((size_t)b * DS + s) * DE))[threadIdx.x] = v;
}

__global__ void init_state_k(const float* __restrict__ hidden, const float* __restrict__ init_att) {
    int idx = blockIdx.x * 256 + threadIdx.x;   // B*H = 32768
    int b = idx >> 9, j = idx & 511;
    g_h0[idx]                = hidden[idx];
    g_hc[b*1024 + j]         = hidden[(size_t)DB*DH + idx];
    g_hc[b*1024 + 512 + j]   = init_att[idx];
}

// GRU gate combine: sums 4+4 K-split partials, applies gates.
__global__ void __launch_bounds__(256) combine_k(const float* __restrict__ hprev, int ldhp,
                                                 float* __restrict__ hout, int ldho,
                                                 float* __restrict__ out, int t, int layer) {
    int idx = blockIdx.x * 256 + threadIdx.x;   // B*H
    int b = idx >> 9, j = idx & 511;
    size_t base = (size_t)b * G3 + j;
    float gir = 0.f, giz = 0.f, gin = 0.f, ghr = 0.f, ghz = 0.f, ghn = 0.f;
#pragma unroll
    for (int p = 0; p < 4; p++) {
        const float* q1 = g_part + (size_t)p       * (DB*G3) + base;
        const float* q2 = g_part + (size_t)(p + 4) * (DB*G3) + base;
        gir += q1[0];  giz += q1[512];  gin += q1[1024];
        ghr += q2[0];  ghz += q2[512];  ghn += q2[1024];
    }
    float r  = sig_f(gir + ghr);
    float zz = sig_f(giz + ghz);
    float n  = tanh_f(gin + r * ghn);
    float h  = (1.f - zz) * n + zz * hprev[(size_t)b * ldhp + j];
    hout[(size_t)b * ldho + j] = h;
    out[OFF_GH + ((size_t)t * 2 + layer) * (DB*DH) + idx] = h;
}

// Fused attention: energy -> softmax -> context -> copy gate.  One block per b.
__global__ void __launch_bounds__(256) attn_k(const float* __restrict__ mask,
                                              const float* __restrict__ Wcopy,
                                              const float* __restrict__ bcopy,
                                              const float* __restrict__ vatt,
                                              float* __restrict__ out, int t) {
    __shared__ float qs[512], vs[512], es[128], red[256];
    int b = blockIdx.x, tid = threadIdx.x;

    for (int a = tid; a < 512; a += 256) {
        float s = g_qp[(size_t)b*512 + a] + g_qp[(size_t)DB*DH + b*512 + a]
                + g_qp[(size_t)2*DB*DH + b*512 + a] + g_qp[(size_t)3*DB*DH + b*512 + a];
        qs[a] = s;
        vs[a] = vatt[a];
    }
    __syncthreads();

    int wid = tid >> 5, lane = tid & 31;
    for (int s = wid; s < DS; s += 8) {
        const float* pr = g_pre + ((size_t)b * DS + s) * 512;
        float acc = 0.f;
#pragma unroll
        for (int i = 0; i < 16; i++) {
            int a = lane + 32 * i;
            acc += vs[a] * tanh_f(pr[a] + qs[a]);
        }
#pragma unroll
        for (int o = 16; o; o >>= 1) acc += __shfl_down_sync(0xffffffffu, acc, o);
        if (lane == 0)
            es[s] = (mask[(size_t)b * DS + s] > 0.5f) ? -1e18f : acc;
    }
    __syncthreads();

    if (wid == 0) {
        float m = -3.4e38f;
#pragma unroll
        for (int i = 0; i < 4; i++) { int s = lane + 32*i; if (s < DS) m = fmaxf(m, es[s]); }
#pragma unroll
        for (int o = 16; o; o >>= 1) m = fmaxf(m, __shfl_xor_sync(0xffffffffu, m, o));
        float p[4]; float sum = 0.f;
#pragma unroll
        for (int i = 0; i < 4; i++) {
            int s = lane + 32*i;
            if (s < DS) { p[i] = fex2((es[s] - m) * L2E); sum += p[i]; }
        }
#pragma unroll
        for (int o = 16; o; o >>= 1) sum += __shfl_xor_sync(0xffffffffu, sum, o);
        float inv = frcp(sum);
#pragma unroll
        for (int i = 0; i < 4; i++) {
            int s = lane + 32*i;
            if (s < DS) {
                float a = p[i] * inv;
                es[s] = a;
                out[OFF_C + ((size_t)t * DB + b) * DS + s] = a;
            }
        }
    }
    __syncthreads();

    // context: ctx[e] = sum_s attn[s] * ctx_bse[b,s,e]
    for (int e = tid; e < 512; e += 256) {
        float acc = 0.f;
        const float* cb = g_ctxbse + (size_t)b * DS * DE + e;
#pragma unroll 4
        for (int s = 0; s < DS; s++) acc += es[s] * cb[(size_t)s * DE];
        g_hc[b*1024 + 512 + e] = acc;
    }
    __syncthreads();

    // copy gate: sigmoid(dot([h1|ctx], W_copy) + b_copy)
    float part = 0.f;
    const float* hr = g_hc + (size_t)b * 1024;
    for (int k = tid; k < 1024; k += 256) part += hr[k] * Wcopy[k];
    red[tid] = part; __syncthreads();
    for (int o = 128; o; o >>= 1) { if (tid < o) red[tid] += red[tid + o]; __syncthreads(); }
    if (tid == 0)
        out[OFF_CP + (size_t)t * DB + b] = sig_f(red[0] + bcopy[0]);
}

// readout partial sum + maxout (pool=2)
__global__ void maxout_k(float* __restrict__ out, int t) {
    int idx = blockIdx.x * 256 + threadIdx.x;   // B*256
    int b = idx >> 8, j = idx & 255;
    const float* re = g_re + ((size_t)t * DB + b) * DH;
    int c0 = 2*j, c1 = 2*j + 1;
    float v0 = re[c0], v1 = re[c1];
#pragma unroll
    for (int p = 0; p < 4; p++) {
        const float* rp = g_rop + (size_t)p * DB * DH + (size_t)b * DH;
        v0 += rp[c0]; v1 += rp[c1];
    }
    out[OFF_G + ((size_t)t * DB + b) * 256 + j] = fmaxf(v0, v1);
}

// final outputs: hid_f, c_last, ctx_f
__global__ void final_k(float* __restrict__ out) {
    int idx = blockIdx.x * 256 + threadIdx.x;  // B*H
    int b = idx >> 9, j = idx & 511;
    out[OFF_HF + idx]                 = g_h0[idx];
    out[OFF_HF + (size_t)DB*DH + idx] = g_hc[b*1024 + j];
    out[OFF_CF + idx]                 = g_hc[b*1024 + 512 + j];
    if (idx < DB * DS)
        out[OFF_CL + idx] = out[OFF_C + (size_t)(DT - 1) * DB * DS + idx];
}

// ---------------------------------------------------------------------------
// host
// ---------------------------------------------------------------------------
static GOp mkop(const float* A, int lda, const float* W, int ldw,
                const float* Ci, int ldci, const float* bias,
                float* C, int ldc, int K) {
    GOp o; o.A = A; o.W = W; o.Ci = Ci; o.bias = bias; o.C = C;
    o.lda = lda; o.ldw = ldw; o.ldci = ldci; o.ldc = ldc; o.K = K;
    return o;
}

extern "C" void kernel_launch(void* const* d_in, const int* in_sizes, int n_in,
                              void* d_out, int out_size) {
    (void)in_sizes; (void)n_in; (void)out_size;
    const int*   inp      = (const int*)  d_in[0];
    const float* hidden   = (const float*)d_in[1];
    const float* context  = (const float*)d_in[2];
    const float* mask     = (const float*)d_in[3];
    const float* init_att = (const float*)d_in[4];
    const float* emb_tab  = (const float*)d_in[5];
    const float* W_ih0    = (const float*)d_in[6];
    const float* W_hh0    = (const float*)d_in[7];
    const float* b_ih0    = (const float*)d_in[8];
    const float* b_hh0    = (const float*)d_in[9];
    const float* W_ih1    = (const float*)d_in[10];
    const float* W_hh1    = (const float*)d_in[11];
    const float* b_ih1    = (const float*)d_in[12];
    const float* b_hh1    = (const float*)d_in[13];
    const float* W_pre    = (const float*)d_in[14];
    const float* b_pre    = (const float*)d_in[15];
    const float* W_q      = (const float*)d_in[16];
    const float* v_att    = (const float*)d_in[17];
    const float* W_copy   = (const float*)d_in[18];
    const float* b_copy   = (const float*)d_in[19];
    const float* W_read   = (const float*)d_in[20];
    const float* b_read   = (const float*)d_in[21];
    float* out = (float*)d_out;

    // scratch addresses (device globals)
    float *p_emb, *p_gi0e, *p_re, *p_pre, *p_ctxbse, *p_h0, *p_hc, *p_part, *p_qp, *p_rop;
    cudaGetSymbolAddress((void**)&p_emb,    g_emb);
    cudaGetSymbolAddress((void**)&p_gi0e,   g_gi0e);
    cudaGetSymbolAddress((void**)&p_re,     g_re);
    cudaGetSymbolAddress((void**)&p_pre,    g_pre);
    cudaGetSymbolAddress((void**)&p_ctxbse, g_ctxbse);
    cudaGetSymbolAddress((void**)&p_h0,     g_h0);
    cudaGetSymbolAddress((void**)&p_hc,     g_hc);
    cudaGetSymbolAddress((void**)&p_part,   g_part);
    cudaGetSymbolAddress((void**)&p_qp,     g_qp);
    cudaGetSymbolAddress((void**)&p_rop,    g_rop);

    const size_t M3 = (size_t)DB * G3;   // one partial buffer stride
    const size_t MH = (size_t)DB * DH;

    // --- precompute -------------------------------------------------------
    gather_emb_k<<<DT*DB, 128>>>(inp, emb_tab);
    transpose_ctx_k<<<dim3(DS, DB), 128>>>(context);
    init_state_k<<<128, 256>>>(hidden, init_att);

    {   // gi0e = emb @ W_ih0[:, :512]^T + b_ih0   (M=4096, N=1536, K=512)
        GOps g; g.op[0] = mkop(p_emb, DW, W_ih0, DW + DE, nullptr, 0, b_ih0, p_gi0e, G3, DW);
        gemm_k<<<dim3(G3/32, (DT*DB)/64, 1), 128>>>(g);
    }
    {   // RE = emb @ W_read[:, :512]^T + b_read   (M=4096, N=512, K=512)
        GOps g; g.op[0] = mkop(p_emb, DW, W_read, DW + DH + DE, nullptr, 0, b_read, p_re, DH, DW);
        gemm_k<<<dim3(DH/32, (DT*DB)/64, 1), 128>>>(g);
    }
    {   // pre = ctx_bse @ W_pre^T + b_pre         (M=6400, N=512, K=512)
        GOps g; g.op[0] = mkop(p_ctxbse, DE, W_pre, DE, nullptr, 0, b_pre, p_pre, 512, DE);
        gemm_k<<<dim3(512/32, (DB*DS)/64, 1), 128>>>(g);
    }

    // --- recurrent loop ---------------------------------------------------
    for (int t = 0; t < DT; t++) {
        {   // GRU0: gi (ctx part, Cinit = gi0e[t]) + gh, K split x4
            GOps g;
            for (int s = 0; s < 4; s++) {
                int ks = 128 * s;
                g.op[s] = mkop(p_hc + 512 + ks, 2*DH, W_ih0 + 512 + ks, DW + DE,
                               (s == 0) ? (p_gi0e + (size_t)t * M3) : nullptr, G3,
                               nullptr, p_part + (size_t)s * M3, G3, 128);
                g.op[4+s] = mkop(p_h0 + ks, DH, W_hh0 + ks, DH,
                                 nullptr, 0, (s == 0) ? b_hh0 : nullptr,
                                 p_part + (size_t)(4+s) * M3, G3, 128);
            }
            gemm_k<<<dim3(G3/32, 1, 8), 128>>>(g);
        }
        combine_k<<<128, 256>>>(p_h0, DH, p_h0, DH, out, t, 0);

        {   // GRU1
            GOps g;
            for (int s = 0; s < 4; s++) {
                int ks = 128 * s;
                g.op[s] = mkop(p_h0 + ks, DH, W_ih1 + ks, DH,
                               nullptr, 0, (s == 0) ? b_ih1 : nullptr,
                               p_part + (size_t)s * M3, G3, 128);
                g.op[4+s] = mkop(p_hc + ks, 2*DH, W_hh1 + ks, DH,
                                 nullptr, 0, (s == 0) ? b_hh1 : nullptr,
                                 p_part + (size_t)(4+s) * M3, G3, 128);
            }
            gemm_k<<<dim3(G3/32, 1, 8), 128>>>(g);
        }
        combine_k<<<128, 256>>>(p_hc, 2*DH, p_hc, 2*DH, out, t, 1);

        {   // q = h1 @ W_q^T, K split x4
            GOps g;
            for (int s = 0; s < 4; s++) {
                int ks = 128 * s;
                g.op[s] = mkop(p_hc + ks, 2*DH, W_q + ks, DH,
                               nullptr, 0, nullptr, p_qp + (size_t)s * MH, DH, 128);
            }
            gemm_k<<<dim3(DH/32, 1, 4), 128>>>(g);
        }

        attn_k<<<DB, 256>>>(mask, W_copy, b_copy, v_att, out, t);

        {   // readout(rest) = [h1|ctx] @ W_read[:, 512:]^T, K=1024 split x4
            GOps g;
            for (int s = 0; s < 4; s++) {
                int ks = 256 * s;
                g.op[s] = mkop(p_hc + ks, 2*DH, W_read + 512 + ks, DW + DH + DE,
                               nullptr, 0, nullptr, p_rop + (size_t)s * MH, DH, 256);
            }
            gemm_k<<<dim3(DH/32, 1, 4), 128>>>(g);
        }

        maxout_k<<<DB, 256>>>(out, t);
    }

    final_k<<<128, 256>>>(out);
}

// round 12
// speedup vs baseline: 1.0023x; 1.0023x over previous
#include <cuda_runtime.h>

// ---------------------------------------------------------------------------
// Problem dims
// ---------------------------------------------------------------------------
#define DT 64
#define DB 64
#define DS 100
#define DH 512
#define DE 512
#define DW 512
#define G3 1536
#define GRIDN 148

// output layout offsets (float elements)
static const size_t OFF_G  = 0;                                  // (T,B,256)
static const size_t OFF_C  = OFF_G  + (size_t)DT*DB*256;         // (T,B,S)
static const size_t OFF_CP = OFF_C  + (size_t)DT*DB*DS;          // (T,B,1)
static const size_t OFF_HF = OFF_CP + (size_t)DT*DB;             // (2,B,H)
static const size_t OFF_CL = OFF_HF + (size_t)2*DB*DH;           // (B,S)
static const size_t OFF_CF = OFF_CL + (size_t)DB*DS;             // (B,E)
static const size_t OFF_GH = OFF_CF + (size_t)DB*DE;             // (T,2,B,H)

// ---------------------------------------------------------------------------
// Device scratch
// ---------------------------------------------------------------------------
__device__ float g_emb   [(size_t)DT*DB*DW];
__device__ float g_gi0e  [(size_t)DT*DB*G3];     // emb @ W_ih0[:, :512]^T + b_ih0
__device__ float g_re    [(size_t)DT*DB*DH];     // emb @ W_read[:, :512]^T + b_read
__device__ float g_pre   [(size_t)DB*DS*DE];     // linear_pre(context) (B,S,A)
__device__ float g_ctxbse[(size_t)DB*DS*DE];     // context (B,S,E)
// packed k-major activations: slot(j,b) = (j>>2)*256 + b*4 + (j&3)
__device__ float g_h0T[2][DB*DH];
__device__ float g_h1T[2][DB*DH];
__device__ float g_ctxT  [DB*DE];
__device__ float g_q     [DB*DH];
__device__ float g_roh   [DB*DH];
__device__ float g_energy[DB*DS];

// grid barrier state (monotone; replay-safe, never reset)
__device__ unsigned long long g_arrive = 0ULL;
__device__ unsigned long long g_epoch  = 0ULL;

// ---------------------------------------------------------------------------
// fast math
// ---------------------------------------------------------------------------
__device__ __forceinline__ float fex2(float x){ float y; asm("ex2.approx.f32 %0, %1;" : "=f"(y) : "f"(x)); return y; }
__device__ __forceinline__ float frcp(float x){ float y; asm("rcp.approx.f32 %0, %1;" : "=f"(y) : "f"(x)); return y; }
#define L2E 1.4426950408889634f

__device__ __forceinline__ float tanh_f(float x){
    float xc = fminf(fmaxf(x, -15.f), 15.f);
    float t  = fex2(xc * (2.f * L2E));
    return (t - 1.f) * frcp(t + 1.f);
}
__device__ __forceinline__ float sig_f(float x){
    float xc = fminf(fmaxf(x, -30.f), 30.f);
    return frcp(1.f + fex2(-xc * L2E));
}

__device__ __forceinline__ int pslot(int j, int b){ return ((j >> 2) << 8) + (b << 2) + (j & 3); }

// ---------------------------------------------------------------------------
// grid barrier (monotone epoch; safe across graph replays)
// ---------------------------------------------------------------------------
__device__ __forceinline__ void gridbar() {
    __syncthreads();
    if (threadIdx.x == 0) {
        __threadfence();
        unsigned long long old = atomicAdd(&g_arrive, 1ULL);
        unsigned long long target = old / GRIDN + 1ULL;
        if (old % GRIDN == GRIDN - 1) {
            atomicAdd(&g_epoch, 1ULL);
        } else {
            while (*((volatile unsigned long long*)&g_epoch) < target) { }
        }
        __threadfence();
    }
    __syncthreads();
}

// ---------------------------------------------------------------------------
// fp32 tiled GEMM for precompute (from R9; ~26 TF/s): C = A@W^T (+Ci)(+bias)
// ---------------------------------------------------------------------------
struct GOp {
    const float* A; const float* W; const float* Ci; const float* bias;
    float* C;
    int lda, ldw, ldci, ldc, K;
};
struct GOps { GOp op[8]; };

__global__ void __launch_bounds__(128) gemm_k(GOps ops) {
    GOp op = ops.op[blockIdx.z];
    __shared__ __align__(16) float As[16][64];
    __shared__ __align__(16) float Ws[16][32];
    int tid = threadIdx.x;
    int tx = tid & 15, ty = tid >> 4;
    int m0 = blockIdx.y << 6, n0 = blockIdx.x << 5;
    int arow = tid >> 1, akh = (tid & 1) << 3;
    const float* Ap = op.A + (size_t)(m0 + arow) * op.lda + akh;
    int wrow = (tid & 63) >> 1, wkh = (tid & 1) << 3;
    const float* Wp = op.W + (size_t)(n0 + wrow) * op.ldw + wkh;
    bool wload = (tid < 64);
    float acc[16];
#pragma unroll
    for (int i = 0; i < 16; i++) acc[i] = 0.f;
    for (int k0 = 0; k0 < op.K; k0 += 16) {
        float4 a0 = *(const float4*)(Ap + k0);
        float4 a1 = *(const float4*)(Ap + k0 + 4);
        As[akh+0][arow] = a0.x; As[akh+1][arow] = a0.y;
        As[akh+2][arow] = a0.z; As[akh+3][arow] = a0.w;
        As[akh+4][arow] = a1.x; As[akh+5][arow] = a1.y;
        As[akh+6][arow] = a1.z; As[akh+7][arow] = a1.w;
        if (wload) {
            float4 w0 = *(const float4*)(Wp + k0);
            float4 w1 = *(const float4*)(Wp + k0 + 4);
            Ws[wkh+0][wrow] = w0.x; Ws[wkh+1][wrow] = w0.y;
            Ws[wkh+2][wrow] = w0.z; Ws[wkh+3][wrow] = w0.w;
            Ws[wkh+4][wrow] = w1.x; Ws[wkh+5][wrow] = w1.y;
            Ws[wkh+6][wrow] = w1.z; Ws[wkh+7][wrow] = w1.w;
        }
        __syncthreads();
#pragma unroll
        for (int k = 0; k < 16; k++) {
            float4 av = *(const float4*)&As[k][tx << 2];
            float4 wv = *(const float4*)&Ws[k][ty << 2];
            float a[4] = {av.x, av.y, av.z, av.w};
            float w[4] = {wv.x, wv.y, wv.z, wv.w};
#pragma unroll
            for (int i = 0; i < 4; i++)
#pragma unroll
                for (int j = 0; j < 4; j++)
                    acc[i*4+j] += a[i] * w[j];
        }
        __syncthreads();
    }
    int nb = n0 + (ty << 2);
#pragma unroll
    for (int i = 0; i < 4; i++) {
        int m = m0 + (tx << 2) + i;
        float v[4];
#pragma unroll
        for (int j = 0; j < 4; j++) {
            float c = acc[i*4+j];
            if (op.Ci)   c += op.Ci[(size_t)m * op.ldci + nb + j];
            if (op.bias) c += op.bias[nb + j];
            v[j] = c;
        }
        float4 o = {v[0], v[1], v[2], v[3]};
        *(float4*)&op.C[(size_t)m * op.ldc + nb] = o;
    }
}

// ---------------------------------------------------------------------------
// precompute helpers
// ---------------------------------------------------------------------------
__global__ void gather_emb_k(const int* __restrict__ inp, const float* __restrict__ tab) {
    int tb = blockIdx.x;
    int idx = inp[tb];
    const float4* src = (const float4*)(tab + (size_t)idx * DW);
    float4* dst = (float4*)(g_emb + (size_t)tb * DW);
    dst[threadIdx.x] = src[threadIdx.x];
}

__global__ void transpose_ctx_k(const float* __restrict__ ctx) {
    int s = blockIdx.x, b = blockIdx.y;
    float4 v = ((const float4*)(ctx + ((size_t)s * DB + b) * DE))[threadIdx.x];
    ((float4*)(g_ctxbse + ((size_t)b * DS + s) * DE))[threadIdx.x] = v;
}

__global__ void init_pack_k(const float* __restrict__ hidden, const float* __restrict__ init_att) {
    int i = blockIdx.x * 256 + threadIdx.x;   // 32768
    int b = i >> 9, j = i & 511;
    int pos = pslot(j, b);
    g_h0T[0][pos] = hidden[i];
    g_h1T[0][pos] = hidden[(size_t)DB*DH + i];
    g_ctxT[pos]   = init_att[i];
}

// ---------------------------------------------------------------------------
// persistent decoder kernel
// ---------------------------------------------------------------------------
struct PP {
    const float* mask; const float* Wcopy; const float* bcopy; const float* vatt;
    const float* W_ih0; const float* W_hh0; const float* b_hh0;
    const float* W_ih1; const float* W_hh1; const float* b_ih1; const float* b_hh1;
    const float* W_q;   const float* W_read;
    float* out;
};

// fused GRU layer phase: blocks 0..127, 4 j-columns each; thread = (b, jj)
__device__ __forceinline__ void gru_phase(
    float* ws, int b, int jj, int j0,
    const float* __restrict__ xp, const float* __restrict__ hp, float* __restrict__ hop,
    const float* __restrict__ Wx, int ldx, int xcol, const float* __restrict__ Wh,
    const float* __restrict__ giB, const float* __restrict__ bhh,
    float* __restrict__ outGH)
{
    int tid = threadIdx.x;
    // stage 24 weight rows (12 x-rows + 12 h-rows) x 512 -> 48KB SMEM
    for (int i = tid; i < 24 * 128; i += 256) {
        int r = i >> 7, k4 = (i & 127) << 2;
        const float* src;
        if (r < 12)      src = Wx + (size_t)((r >> 2) * 512 + j0 + (r & 3)) * ldx + xcol + k4;
        else { int rr = r - 12; src = Wh + (size_t)((rr >> 2) * 512 + j0 + (rr & 3)) * 512 + k4; }
        *(float4*)(ws + r * 512 + k4) = *(const float4*)src;
    }
    __syncthreads();
    int j = j0 + jj;
    float air = giB[j], aiz = giB[j + 512], ain = giB[j + 1024];
    float ahr = bhh[j], ahz = bhh[j + 512], ahn = bhh[j + 1024];
    const float* wxr = ws + jj * 512;
    const float* wxz = wxr + 4 * 512;
    const float* wxn = wxr + 8 * 512;
    const float* whr = ws + (12 + jj) * 512;
    const float* whz = whr + 4 * 512;
    const float* whn = whr + 8 * 512;
#pragma unroll 4
    for (int k4 = 0; k4 < 128; k4++) {
        float4 a = *(const float4*)(xp + k4 * 256 + b * 4);
        float4 h = *(const float4*)(hp + k4 * 256 + b * 4);
        float4 w;
        w = *(const float4*)(wxr + k4 * 4); air += a.x*w.x + a.y*w.y + a.z*w.z + a.w*w.w;
        w = *(const float4*)(wxz + k4 * 4); aiz += a.x*w.x + a.y*w.y + a.z*w.z + a.w*w.w;
        w = *(const float4*)(wxn + k4 * 4); ain += a.x*w.x + a.y*w.y + a.z*w.z + a.w*w.w;
        w = *(const float4*)(whr + k4 * 4); ahr += h.x*w.x + h.y*w.y + h.z*w.z + h.w*w.w;
        w = *(const float4*)(whz + k4 * 4); ahz += h.x*w.x + h.y*w.y + h.z*w.z + h.w*w.w;
        w = *(const float4*)(whn + k4 * 4); ahn += h.x*w.x + h.y*w.y + h.z*w.z + h.w*w.w;
    }
    float r  = sig_f(air + ahr);
    float z  = sig_f(aiz + ahz);
    float n  = tanh_f(ain + r * ahn);
    float hprev = hp[pslot(j, b)];
    float hnew  = (1.f - z) * n + z * hprev;
    hop[pslot(j, b)] = hnew;
    outGH[b * 512 + j] = hnew;
}

__global__ void __launch_bounds__(256, 1) persist_k(PP p) {
    __shared__ float ws[12288];   // 48KB, reused per phase
    int tid = threadIdx.x, bi = blockIdx.x;
    int b = tid & 63, jj = tid >> 6;

    for (int t = 0; t < DT; t++) {
        int rp = t & 1, wp = rp ^ 1;

        // ---- A: GRU layer 0 (x = ctx feed, precomputed emb part in gi0e) ----
        if (bi < 128) {
            gru_phase(ws, b, jj, bi * 4,
                      g_ctxT, g_h0T[rp], g_h0T[wp],
                      p.W_ih0, DW + DE, 512, p.W_hh0,
                      g_gi0e + ((size_t)t * DB + b) * G3 - (size_t)0, p.b_hh0,
                      p.out + OFF_GH + ((size_t)t * 2 + 0) * (DB * DH));
        }
        gridbar();

        // ---- C: GRU layer 1 (x = h0_new) ----
        if (bi < 128) {
            gru_phase(ws, b, jj, bi * 4,
                      g_h0T[wp], g_h1T[rp], g_h1T[wp],
                      p.W_ih1, DH, 0, p.W_hh1,
                      p.b_ih1, p.b_hh1,
                      p.out + OFF_GH + ((size_t)t * 2 + 1) * (DB * DH));
        }
        gridbar();

        // ---- E: q = h1@Wq^T  and  roh = h1@W_read[:,512:1024]^T ----
        if (bi < 128) {
            int c0 = bi * 8;
            for (int i = tid; i < 8 * 128; i += 256) {
                int r = i >> 7, k4 = (i & 127) << 2, c = c0 + r;
                const float* src = (c < 512) ? (p.W_q + (size_t)c * 512 + k4)
                                             : (p.W_read + (size_t)(c - 512) * G3 + 512 + k4);
                *(float4*)(ws + r * 512 + k4) = *(const float4*)src;
            }
            __syncthreads();
            const float* h1w = g_h1T[wp];
            const float* w0 = ws + jj * 512;
            const float* w1 = ws + (jj + 4) * 512;
            float a0 = 0.f, a1 = 0.f;
#pragma unroll 4
            for (int k4 = 0; k4 < 128; k4++) {
                float4 a = *(const float4*)(h1w + k4 * 256 + b * 4);
                float4 x = *(const float4*)(w0 + k4 * 4);
                a0 += a.x*x.x + a.y*x.y + a.z*x.z + a.w*x.w;
                float4 y = *(const float4*)(w1 + k4 * 4);
                a1 += a.x*y.x + a.y*y.y + a.z*y.z + a.w*y.w;
            }
            int c = c0 + jj;
            if (c < 512) g_q[b * 512 + c] = a0; else g_roh[b * 512 + c - 512] = a0;
            c = c0 + jj + 4;
            if (c < 512) g_q[b * 512 + c] = a1; else g_roh[b * 512 + c - 512] = a1;
        }
        gridbar();

        // ---- F1: attention energies over all (b,s) pairs ----
        {
            int gw = bi * 8 + (tid >> 5), lane = tid & 31;
            for (int idx = gw; idx < DB * DS; idx += GRIDN * 8) {
                int bb = idx / DS, s = idx - bb * DS;
                const float* pr = g_pre + (size_t)idx * 512;
                const float* qq = g_q + (size_t)bb * 512;
                float acc = 0.f;
#pragma unroll
                for (int i4 = 0; i4 < 4; i4++) {
                    int a0i = i4 * 128 + lane * 4;
                    float4 pv = *(const float4*)(pr + a0i);
                    float4 qv = *(const float4*)(qq + a0i);
                    float4 vv = *(const float4*)(p.vatt + a0i);
                    acc += vv.x * tanh_f(pv.x + qv.x);
                    acc += vv.y * tanh_f(pv.y + qv.y);
                    acc += vv.z * tanh_f(pv.z + qv.z);
                    acc += vv.w * tanh_f(pv.w + qv.w);
                }
#pragma unroll
                for (int o = 16; o; o >>= 1) acc += __shfl_down_sync(0xffffffffu, acc, o);
                if (lane == 0)
                    g_energy[idx] = (p.mask[idx] > 0.5f) ? -1e18f : acc;
            }
        }
        gridbar();

        // ---- F2: softmax + context + copy gate (one block per b) ----
        if (bi < DB) {
            int b2 = bi;
            float* es  = ws;          // 128
            float* red = ws + 128;    // 256
            for (int s = tid; s < DS; s += 256) es[s] = g_energy[b2 * DS + s];
            __syncthreads();
            if (tid < 32) {
                int lane = tid;
                float m = -3.4e38f;
#pragma unroll
                for (int i = 0; i < 4; i++) { int s = lane + 32 * i; if (s < DS) m = fmaxf(m, es[s]); }
#pragma unroll
                for (int o = 16; o; o >>= 1) m = fmaxf(m, __shfl_xor_sync(0xffffffffu, m, o));
                float pr4[4]; float sum = 0.f;
#pragma unroll
                for (int i = 0; i < 4; i++) {
                    int s = lane + 32 * i;
                    if (s < DS) { pr4[i] = fex2((es[s] - m) * L2E); sum += pr4[i]; }
                }
#pragma unroll
                for (int o = 16; o; o >>= 1) sum += __shfl_xor_sync(0xffffffffu, sum, o);
                float inv = frcp(sum);
#pragma unroll
                for (int i = 0; i < 4; i++) {
                    int s = lane + 32 * i;
                    if (s < DS) {
                        float a = pr4[i] * inv;
                        es[s] = a;
                        p.out[OFF_C + ((size_t)t * DB + b2) * DS + s] = a;
                        if (t == DT - 1) p.out[OFF_CL + (size_t)b2 * DS + s] = a;
                    }
                }
            }
            __syncthreads();
            for (int e = tid; e < 512; e += 256) {
                float acc = 0.f;
                const float* cb = g_ctxbse + (size_t)b2 * DS * DE + e;
#pragma unroll 4
                for (int s = 0; s < DS; s++) acc += es[s] * cb[(size_t)s * DE];
                g_ctxT[pslot(e, b2)] = acc;
            }
            __syncthreads();
            float part = 0.f;
            const float* h1w = g_h1T[wp];
            for (int k = tid; k < 1024; k += 256) {
                float v = (k < 512) ? h1w[pslot(k, b2)] : g_ctxT[pslot(k - 512, b2)];
                part += v * p.Wcopy[k];
            }
            red[tid] = part; __syncthreads();
            for (int o = 128; o; o >>= 1) { if (tid < o) red[tid] += red[tid + o]; __syncthreads(); }
            if (tid == 0)
                p.out[OFF_CP + (size_t)t * DB + b2] = sig_f(red[0] + p.bcopy[0]);
        }
        gridbar();

        // ---- G: ro_ctx = ctx@W_read[:,1024:]^T, + re + roh, maxout ----
        // (no barrier after: next A never touches G's buffers; A->C barrier
        //  guarantees all G work done before E(t+1) overwrites roh)
        if (bi < 128) {
            int c0 = bi * 4;
            for (int i = tid; i < 4 * 128; i += 256) {
                int r = i >> 7, k4 = (i & 127) << 2;
                const float* src = p.W_read + (size_t)(c0 + r) * G3 + 1024 + k4;
                *(float4*)(ws + r * 512 + k4) = *(const float4*)src;
            }
            __syncthreads();
            int pr2 = jj & 1, kh = jj >> 1;
            const float* wA = ws + (2 * pr2) * 512 + kh * 256;
            const float* wB = ws + (2 * pr2 + 1) * 512 + kh * 256;
            const float* ap = g_ctxT + kh * 64 * 256;
            float a0 = 0.f, a1 = 0.f;
#pragma unroll 4
            for (int k4 = 0; k4 < 64; k4++) {
                float4 a = *(const float4*)(ap + k4 * 256 + b * 4);
                float4 w = *(const float4*)(wA + k4 * 4);
                a0 += a.x*w.x + a.y*w.y + a.z*w.z + a.w*w.w;
                float4 v = *(const float4*)(wB + k4 * 4);
                a1 += a.x*v.x + a.y*v.y + a.z*v.z + a.w*v.w;
            }
            float* pp = ws + 2048;
            pp[tid] = a0; pp[256 + tid] = a1;
            __syncthreads();
            if (jj < 2) {
                float s0 = pp[tid] + pp[tid + 128];
                float s1 = pp[256 + tid] + pp[256 + tid + 128];
                int c = c0 + 2 * pr2;
                const float* re = g_re + ((size_t)t * DB + b) * DH;
                const float* rh = g_roh + (size_t)b * DH;
                float v0 = re[c]     + rh[c]     + s0;
                float v1 = re[c + 1] + rh[c + 1] + s1;
                p.out[OFF_G + ((size_t)t * DB + b) * 256 + (c >> 1)] = fmaxf(v0, v1);
            }
            __syncthreads();   // protect ws before next step's staging
        }
    }

    gridbar();
    // final outputs: hid_f, ctx_f  (step 63 wrote buffers index 0)
    for (int i = bi * 256 + tid; i < DB * DH; i += GRIDN * 256) {
        int bb = i >> 9, j = i & 511;
        int pos = pslot(j, bb);
        p.out[OFF_HF + i]                    = g_h0T[0][pos];
        p.out[OFF_HF + (size_t)DB*DH + i]    = g_h1T[0][pos];
        p.out[OFF_CF + i]                    = g_ctxT[pos];
    }
}

// ---------------------------------------------------------------------------
// host
// ---------------------------------------------------------------------------
static GOp mkop(const float* A, int lda, const float* W, int ldw,
                const float* Ci, int ldci, const float* bias,
                float* C, int ldc, int K) {
    GOp o; o.A = A; o.W = W; o.Ci = Ci; o.bias = bias; o.C = C;
    o.lda = lda; o.ldw = ldw; o.ldci = ldci; o.ldc = ldc; o.K = K;
    return o;
}

extern "C" void kernel_launch(void* const* d_in, const int* in_sizes, int n_in,
                              void* d_out, int out_size) {
    (void)in_sizes; (void)n_in; (void)out_size;
    const int*   inp      = (const int*)  d_in[0];
    const float* hidden   = (const float*)d_in[1];
    const float* context  = (const float*)d_in[2];
    const float* mask     = (const float*)d_in[3];
    const float* init_att = (const float*)d_in[4];
    const float* emb_tab  = (const float*)d_in[5];
    const float* W_ih0    = (const float*)d_in[6];
    const float* W_hh0    = (const float*)d_in[7];
    const float* b_ih0    = (const float*)d_in[8];
    const float* b_hh0    = (const float*)d_in[9];
    const float* W_ih1    = (const float*)d_in[10];
    const float* W_hh1    = (const float*)d_in[11];
    const float* b_ih1    = (const float*)d_in[12];
    const float* b_hh1    = (const float*)d_in[13];
    const float* W_pre    = (const float*)d_in[14];
    const float* b_pre    = (const float*)d_in[15];
    const float* W_q      = (const float*)d_in[16];
    const float* v_att    = (const float*)d_in[17];
    const float* W_copy   = (const float*)d_in[18];
    const float* b_copy   = (const float*)d_in[19];
    const float* W_read   = (const float*)d_in[20];
    const float* b_read   = (const float*)d_in[21];
    float* out = (float*)d_out;

    float *p_emb, *p_gi0e, *p_re, *p_pre, *p_ctxbse;
    cudaGetSymbolAddress((void**)&p_emb,    g_emb);
    cudaGetSymbolAddress((void**)&p_gi0e,   g_gi0e);
    cudaGetSymbolAddress((void**)&p_re,     g_re);
    cudaGetSymbolAddress((void**)&p_pre,    g_pre);
    cudaGetSymbolAddress((void**)&p_ctxbse, g_ctxbse);

    // --- precompute -------------------------------------------------------
    gather_emb_k<<<DT*DB, 128>>>(inp, emb_tab);
    transpose_ctx_k<<<dim3(DS, DB), 128>>>(context);
    init_pack_k<<<128, 256>>>(hidden, init_att);

    {   // gi0e = emb @ W_ih0[:, :512]^T + b_ih0   (M=4096, N=1536, K=512)
        GOps g; g.op[0] = mkop(p_emb, DW, W_ih0, DW + DE, nullptr, 0, b_ih0, p_gi0e, G3, DW);
        gemm_k<<<dim3(G3/32, (DT*DB)/64, 1), 128>>>(g);
    }
    {   // re = emb @ W_read[:, :512]^T + b_read   (M=4096, N=512, K=512)
        GOps g; g.op[0] = mkop(p_emb, DW, W_read, DW + DH + DE, nullptr, 0, b_read, p_re, DH, DW);
        gemm_k<<<dim3(DH/32, (DT*DB)/64, 1), 128>>>(g);
    }
    {   // pre = ctx_bse @ W_pre^T + b_pre         (M=6400, N=512, K=512)
        GOps g; g.op[0] = mkop(p_ctxbse, DE, W_pre, DE, nullptr, 0, b_pre, p_pre, 512, DE);
        gemm_k<<<dim3(512/32, (DB*DS)/64, 1), 128>>>(g);
    }

    // --- persistent recurrent kernel -------------------------------------
    PP pp;
    pp.mask = mask; pp.Wcopy = W_copy; pp.bcopy = b_copy; pp.vatt = v_att;
    pp.W_ih0 = W_ih0; pp.W_hh0 = W_hh0; pp.b_hh0 = b_hh0;
    pp.W_ih1 = W_ih1; pp.W_hh1 = W_hh1; pp.b_ih1 = b_ih1; pp.b_hh1 = b_hh1;
    pp.W_q = W_q; pp.W_read = W_read;
    pp.out = out;
    persist_k<<<GRIDN, 256>>>(pp);
}

// round 14
// speedup vs baseline: 1.0877x; 1.0852x over previous
#include <cuda_runtime.h>

// ---------------------------------------------------------------------------
// Problem dims
// ---------------------------------------------------------------------------
#define DT 64
#define DB 64
#define DS 100
#define DH 512
#define DE 512
#define DW 512
#define G3 1536
#define GRIDN 148
#define NTHR 256

// output layout offsets (float elements)
static const size_t OFF_G  = 0;                                  // (T,B,256)
static const size_t OFF_C  = OFF_G  + (size_t)DT*DB*256;         // (T,B,S)
static const size_t OFF_CP = OFF_C  + (size_t)DT*DB*DS;          // (T,B,1)
static const size_t OFF_HF = OFF_CP + (size_t)DT*DB;             // (2,B,H)
static const size_t OFF_CL = OFF_HF + (size_t)2*DB*DH;           // (B,S)
static const size_t OFF_CF = OFF_CL + (size_t)DB*DS;             // (B,E)
static const size_t OFF_GH = OFF_CF + (size_t)DB*DE;             // (T,2,B,H)

// dynamic smem layout (float offsets)
#define SW_A   0        // GRU0: 24 rows x 512
#define SW_C   12288    // GRU1: 24 rows x 512
#define SW_Q   24576    // q:     4 rows x 512
#define SW_R1  26624    // roh:   4 rows x 512
#define SW_SC  28672    // F2 scratch (es 128 + red 256)
#define SW_TOT 29184    // 116736 bytes

// ---------------------------------------------------------------------------
// Device scratch
// ---------------------------------------------------------------------------
__device__ float g_emb   [(size_t)DT*DB*DW];
__device__ float g_gi0e  [(size_t)DT*DB*G3];
__device__ float g_re    [(size_t)DT*DB*DH];
__device__ float g_pre   [(size_t)DB*DS*DE];
__device__ float g_ctxbse[(size_t)DB*DS*DE];
// packed k-major activations: slot(j,b) = (j>>2)*256 + b*4 + (j&3)
__device__ float g_h0T[2][DB*DH];
__device__ float g_h1T[2][DB*DH];
__device__ float g_ctxT  [DB*DE];
__device__ float g_q     [DB*DH];
__device__ float g_roh[2][DB*DH];
__device__ float g_energy[DB*DS];

// grid barrier state (monotone; replay-safe) — separate cache lines
__device__ __align__(128) unsigned long long g_arrive = 0ULL;
__device__ __align__(128) unsigned long long g_epoch  = 0ULL;

// ---------------------------------------------------------------------------
// fast math
// ---------------------------------------------------------------------------
__device__ __forceinline__ float fex2(float x){ float y; asm("ex2.approx.f32 %0, %1;" : "=f"(y) : "f"(x)); return y; }
__device__ __forceinline__ float frcp(float x){ float y; asm("rcp.approx.f32 %0, %1;" : "=f"(y) : "f"(x)); return y; }
#define L2E 1.4426950408889634f

__device__ __forceinline__ float tanh_f(float x){
    float xc = fminf(fmaxf(x, -15.f), 15.f);
    float t  = fex2(xc * (2.f * L2E));
    return (t - 1.f) * frcp(t + 1.f);
}
__device__ __forceinline__ float sig_f(float x){
    float xc = fminf(fmaxf(x, -30.f), 30.f);
    return frcp(1.f + fex2(-xc * L2E));
}

__device__ __forceinline__ int pslot(int j, int b){ return ((j >> 2) << 8) + (b << 2) + (j & 3); }

// ---------------------------------------------------------------------------
// grid barrier
// ---------------------------------------------------------------------------
__device__ __forceinline__ void gridbar() {
    __syncthreads();
    if (threadIdx.x == 0) {
        __threadfence();
        unsigned long long old = atomicAdd(&g_arrive, 1ULL);
        unsigned long long target = old / GRIDN + 1ULL;
        if (old % GRIDN == GRIDN - 1) {
            atomicAdd(&g_epoch, 1ULL);
        } else {
            while (*((volatile unsigned long long*)&g_epoch) < target) { }
        }
        __threadfence();
    }
    __syncthreads();
}

// ---------------------------------------------------------------------------
// fp32 tiled GEMM for precompute (unchanged, proven)
// ---------------------------------------------------------------------------
struct GOp {
    const float* A; const float* W; const float* Ci; const float* bias;
    float* C;
    int lda, ldw, ldci, ldc, K;
};
struct GOps { GOp op[8]; };

__global__ void __launch_bounds__(128) gemm_k(GOps ops) {
    GOp op = ops.op[blockIdx.z];
    __shared__ __align__(16) float As[16][64];
    __shared__ __align__(16) float Ws[16][32];
    int tid = threadIdx.x;
    int tx = tid & 15, ty = tid >> 4;
    int m0 = blockIdx.y << 6, n0 = blockIdx.x << 5;
    int arow = tid >> 1, akh = (tid & 1) << 3;
    const float* Ap = op.A + (size_t)(m0 + arow) * op.lda + akh;
    int wrow = (tid & 63) >> 1, wkh = (tid & 1) << 3;
    const float* Wp = op.W + (size_t)(n0 + wrow) * op.ldw + wkh;
    bool wload = (tid < 64);
    float acc[16];
#pragma unroll
    for (int i = 0; i < 16; i++) acc[i] = 0.f;
    for (int k0 = 0; k0 < op.K; k0 += 16) {
        float4 a0 = *(const float4*)(Ap + k0);
        float4 a1 = *(const float4*)(Ap + k0 + 4);
        As[akh+0][arow] = a0.x; As[akh+1][arow] = a0.y;
        As[akh+2][arow] = a0.z; As[akh+3][arow] = a0.w;
        As[akh+4][arow] = a1.x; As[akh+5][arow] = a1.y;
        As[akh+6][arow] = a1.z; As[akh+7][arow] = a1.w;
        if (wload) {
            float4 w0 = *(const float4*)(Wp + k0);
            float4 w1 = *(const float4*)(Wp + k0 + 4);
            Ws[wkh+0][wrow] = w0.x; Ws[wkh+1][wrow] = w0.y;
            Ws[wkh+2][wrow] = w0.z; Ws[wkh+3][wrow] = w0.w;
            Ws[wkh+4][wrow] = w1.x; Ws[wkh+5][wrow] = w1.y;
            Ws[wkh+6][wrow] = w1.z; Ws[wkh+7][wrow] = w1.w;
        }
        __syncthreads();
#pragma unroll
        for (int k = 0; k < 16; k++) {
            float4 av = *(const float4*)&As[k][tx << 2];
            float4 wv = *(const float4*)&Ws[k][ty << 2];
            float a[4] = {av.x, av.y, av.z, av.w};
            float w[4] = {wv.x, wv.y, wv.z, wv.w};
#pragma unroll
            for (int i = 0; i < 4; i++)
#pragma unroll
                for (int j = 0; j < 4; j++)
                    acc[i*4+j] += a[i] * w[j];
        }
        __syncthreads();
    }
    int nb = n0 + (ty << 2);
#pragma unroll
    for (int i = 0; i < 4; i++) {
        int m = m0 + (tx << 2) + i;
        float v[4];
#pragma unroll
        for (int j = 0; j < 4; j++) {
            float c = acc[i*4+j];
            if (op.Ci)   c += op.Ci[(size_t)m * op.ldci + nb + j];
            if (op.bias) c += op.bias[nb + j];
            v[j] = c;
        }
        float4 o = {v[0], v[1], v[2], v[3]};
        *(float4*)&op.C[(size_t)m * op.ldc + nb] = o;
    }
}

// ---------------------------------------------------------------------------
// precompute helpers
// ---------------------------------------------------------------------------
__global__ void gather_emb_k(const int* __restrict__ inp, const float* __restrict__ tab) {
    int tb = blockIdx.x;
    int idx = inp[tb];
    const float4* src = (const float4*)(tab + (size_t)idx * DW);
    float4* dst = (float4*)(g_emb + (size_t)tb * DW);
    dst[threadIdx.x] = src[threadIdx.x];
}

__global__ void transpose_ctx_k(const float* __restrict__ ctx) {
    int s = blockIdx.x, b = blockIdx.y;
    float4 v = ((const float4*)(ctx + ((size_t)s * DB + b) * DE))[threadIdx.x];
    ((float4*)(g_ctxbse + ((size_t)b * DS + s) * DE))[threadIdx.x] = v;
}

__global__ void init_pack_k(const float* __restrict__ hidden, const float* __restrict__ init_att) {
    int i = blockIdx.x * 256 + threadIdx.x;
    int b = i >> 9, j = i & 511;
    int pos = pslot(j, b);
    g_h0T[0][pos] = hidden[i];
    g_h1T[0][pos] = hidden[(size_t)DB*DH + i];
    g_ctxT[pos]   = init_att[i];
}

// ---------------------------------------------------------------------------
// persistent decoder
// ---------------------------------------------------------------------------
struct PP {
    const float* mask; const float* Wcopy; const float* bcopy; const float* vatt;
    const float* W_ih0; const float* W_hh0; const float* b_hh0;
    const float* W_ih1; const float* W_hh1; const float* b_ih1; const float* b_hh1;
    const float* W_q;   const float* W_read;
    float* out;
};

// GRU with resident weights; no internal syncs.
__device__ __forceinline__ void gru_do(
    const float* __restrict__ w, int b, int jj, int j,
    const float* __restrict__ xp, const float* __restrict__ hp, float* __restrict__ hop,
    float air, float aiz, float ain, float ahr, float ahz, float ahn,
    float* __restrict__ outGH)
{
    const float* wxr = w + jj * 512;
    const float* wxz = wxr + 2048;
    const float* wxn = wxr + 4096;
    const float* whr = w + (12 + jj) * 512;
    const float* whz = whr + 2048;
    const float* whn = whr + 4096;
#pragma unroll 4
    for (int k4 = 0; k4 < 128; k4++) {
        float4 a = *(const float4*)(xp + k4 * 256 + b * 4);
        float4 h = *(const float4*)(hp + k4 * 256 + b * 4);
        float4 wv;
        wv = *(const float4*)(wxr + k4 * 4); air += a.x*wv.x + a.y*wv.y + a.z*wv.z + a.w*wv.w;
        wv = *(const float4*)(wxz + k4 * 4); aiz += a.x*wv.x + a.y*wv.y + a.z*wv.z + a.w*wv.w;
        wv = *(const float4*)(wxn + k4 * 4); ain += a.x*wv.x + a.y*wv.y + a.z*wv.z + a.w*wv.w;
        wv = *(const float4*)(whr + k4 * 4); ahr += h.x*wv.x + h.y*wv.y + h.z*wv.z + h.w*wv.w;
        wv = *(const float4*)(whz + k4 * 4); ahz += h.x*wv.x + h.y*wv.y + h.z*wv.z + h.w*wv.w;
        wv = *(const float4*)(whn + k4 * 4); ahn += h.x*wv.x + h.y*wv.y + h.z*wv.z + h.w*wv.w;
    }
    float r  = sig_f(air + ahr);
    float z  = sig_f(aiz + ahz);
    float n  = tanh_f(ain + r * ahn);
    float hprev = hp[pslot(j, b)];
    float hnew  = (1.f - z) * n + z * hprev;
    hop[pslot(j, b)] = hnew;
    outGH[b * 512 + j] = hnew;
}

// readout-ctx partial (blocks 128..143): 8 cols per thread, e4 range
__device__ __forceinline__ void tail_part(float* acc, const float* __restrict__ wrc,
                                          int tb, int tcg, int e4lo, int e4hi) {
#pragma unroll 2
    for (int e4 = e4lo; e4 < e4hi; e4++) {
        float4 a = *(const float4*)(g_ctxT + e4 * 256 + tb * 4);
#pragma unroll
        for (int c = 0; c < 8; c++) {
            float4 w = *(const float4*)(wrc + (tcg * 8 + c) * 512 + e4 * 4);
            acc[c] += a.x*w.x + a.y*w.y + a.z*w.z + a.w*w.w;
        }
    }
}

__device__ __forceinline__ void tail_write(const float* acc, int tt, int tb, int tc0,
                                           float* __restrict__ out) {
    const float* re = g_re + ((size_t)tt * DB + tb) * DH + tc0;
    const float* rh = g_roh[tt & 1] + (size_t)tb * DH + tc0;
#pragma unroll
    for (int p = 0; p < 4; p++) {
        float v0 = acc[2*p]     + re[2*p]     + rh[2*p];
        float v1 = acc[2*p + 1] + re[2*p + 1] + rh[2*p + 1];
        out[OFF_G + ((size_t)tt * DB + tb) * 256 + ((tc0 >> 1) + p)] = fmaxf(v0, v1);
    }
}

extern __shared__ float ws[];

__global__ void __launch_bounds__(NTHR, 1) persist_k(PP p) {
    int tid = threadIdx.x, bi = blockIdx.x;
    int b = tid & 63, jj = tid >> 6;

    // ---- one-time weight residency ----
    if (bi < 128) {
        int j0 = bi * 4;
        for (int i = tid; i < 24 * 128; i += NTHR) {          // GRU0
            int r = i >> 7, k4 = (i & 127) << 2;
            const float* src = (r < 12)
                ? p.W_ih0 + (size_t)((r >> 2) * 512 + j0 + (r & 3)) * 1024 + 512 + k4
                : p.W_hh0 + (size_t)((((r - 12) >> 2)) * 512 + j0 + ((r - 12) & 3)) * 512 + k4;
            *(float4*)(ws + SW_A + r * 512 + k4) = *(const float4*)src;
        }
        for (int i = tid; i < 24 * 128; i += NTHR) {          // GRU1
            int r = i >> 7, k4 = (i & 127) << 2;
            const float* src = (r < 12)
                ? p.W_ih1 + (size_t)((r >> 2) * 512 + j0 + (r & 3)) * 512 + k4
                : p.W_hh1 + (size_t)((((r - 12) >> 2)) * 512 + j0 + ((r - 12) & 3)) * 512 + k4;
            *(float4*)(ws + SW_C + r * 512 + k4) = *(const float4*)src;
        }
        for (int i = tid; i < 4 * 128; i += NTHR) {           // q rows
            int r = i >> 7, k4 = (i & 127) << 2;
            *(float4*)(ws + SW_Q + r * 512 + k4) =
                *(const float4*)(p.W_q + (size_t)(j0 + r) * 512 + k4);
        }
        for (int i = tid; i < 4 * 128; i += NTHR) {           // roh rows
            int r = i >> 7, k4 = (i & 127) << 2;
            *(float4*)(ws + SW_R1 + r * 512 + k4) =
                *(const float4*)(p.W_read + (size_t)(j0 + r) * G3 + 512 + k4);
        }
    } else if (bi < 144) {
        int c0 = (bi - 128) * 32;
        for (int i = tid; i < 32 * 128; i += NTHR) {          // readout-ctx rows
            int r = i >> 7, k4 = (i & 127) << 2;
            *(float4*)(ws + r * 512 + k4) =
                *(const float4*)(p.W_read + (size_t)(c0 + r) * G3 + 1024 + k4);
        }
    }
    __syncthreads();

    int j = bi * 4 + jj;                       // owned column (bi<128)
    float b0r=0,b0z=0,b0n=0, b1ir=0,b1iz=0,b1in=0, b1hr=0,b1hz=0,b1hn=0;
    if (bi < 128) {
        b0r  = p.b_hh0[j];  b0z  = p.b_hh0[j + 512];  b0n  = p.b_hh0[j + 1024];
        b1ir = p.b_ih1[j];  b1iz = p.b_ih1[j + 512];  b1in = p.b_ih1[j + 1024];
        b1hr = p.b_hh1[j];  b1hz = p.b_hh1[j + 512];  b1hn = p.b_hh1[j + 1024];
    }
    int tb = tid & 63, tcg = tid >> 6;
    int tc0 = (bi - 128) * 32 + tcg * 8;       // tail cols (bi 128..143)
    float tacc[8];

    for (int t = 0; t < DT; t++) {
        int rp = t & 1, wp = rp ^ 1;

        // ---- A: GRU0 || tail-part1(t-1) ----
        if (bi < 128) {
            const float* giB = g_gi0e + ((size_t)t * DB + b) * G3;
            gru_do(ws + SW_A, b, jj, j, g_ctxT, g_h0T[rp], g_h0T[wp],
                   giB[j], giB[j + 512], giB[j + 1024], b0r, b0z, b0n,
                   p.out + OFF_GH + ((size_t)t * 2 + 0) * (DB * DH));
        } else if (bi < 144 && t > 0) {
#pragma unroll
            for (int c = 0; c < 8; c++) tacc[c] = 0.f;
            tail_part(tacc, ws, tb, tcg, 0, 64);
        }
        gridbar();

        // ---- C: GRU1 || tail-part2(t-1) ----
        if (bi < 128) {
            gru_do(ws + SW_C, b, jj, j, g_h0T[wp], g_h1T[rp], g_h1T[wp],
                   b1ir, b1iz, b1in, b1hr, b1hz, b1hn,
                   p.out + OFF_GH + ((size_t)t * 2 + 1) * (DB * DH));
        } else if (bi < 144 && t > 0) {
            tail_part(tacc, ws, tb, tcg, 64, 128);
        }
        gridbar();

        // ---- E: q + roh || tail-write(t-1) ----
        if (bi < 128) {
            const float* h1w = g_h1T[wp];
            const float* wq = ws + SW_Q  + jj * 512;
            const float* wr = ws + SW_R1 + jj * 512;
            float aq = 0.f, ar = 0.f;
#pragma unroll 4
            for (int k4 = 0; k4 < 128; k4++) {
                float4 a = *(const float4*)(h1w + k4 * 256 + b * 4);
                float4 x = *(const float4*)(wq + k4 * 4);
                aq += a.x*x.x + a.y*x.y + a.z*x.z + a.w*x.w;
                float4 y = *(const float4*)(wr + k4 * 4);
                ar += a.x*y.x + a.y*y.y + a.z*y.z + a.w*y.w;
            }
            g_q[b * 512 + j] = aq;
            g_roh[t & 1][b * 512 + j] = ar;
        } else if (bi < 144 && t > 0) {
            tail_write(tacc, t - 1, tb, tc0, p.out);
        }
        gridbar();

        // ---- F1: attention energies ----
        {
            int gw = bi * 8 + (tid >> 5), lane = tid & 31;
            for (int idx = gw; idx < DB * DS; idx += GRIDN * 8) {
                int bb = idx / DS;
                const float* pr = g_pre + (size_t)idx * 512;
                const float* qq = g_q + (size_t)bb * 512;
                float acc = 0.f;
#pragma unroll
                for (int i4 = 0; i4 < 4; i4++) {
                    int a0i = i4 * 128 + lane * 4;
                    float4 pv = *(const float4*)(pr + a0i);
                    float4 qv = *(const float4*)(qq + a0i);
                    float4 vv = *(const float4*)(p.vatt + a0i);
                    acc += vv.x * tanh_f(pv.x + qv.x);
                    acc += vv.y * tanh_f(pv.y + qv.y);
                    acc += vv.z * tanh_f(pv.z + qv.z);
                    acc += vv.w * tanh_f(pv.w + qv.w);
                }
#pragma unroll
                for (int o = 16; o; o >>= 1) acc += __shfl_down_sync(0xffffffffu, acc, o);
                if (lane == 0)
                    g_energy[idx] = (p.mask[idx] > 0.5f) ? -1e18f : acc;
            }
        }
        gridbar();

        // ---- F2: softmax + context + copy (blocks 0..63) ----
        if (bi < DB) {
            int b2 = bi;
            float* es  = ws + SW_SC;
            float* red = ws + SW_SC + 128;
            for (int s = tid; s < DS; s += NTHR) es[s] = g_energy[b2 * DS + s];
            __syncthreads();
            if (tid < 32) {
                int lane = tid;
                float m = -3.4e38f;
#pragma unroll
                for (int i = 0; i < 4; i++) { int s = lane + 32 * i; if (s < DS) m = fmaxf(m, es[s]); }
#pragma unroll
                for (int o = 16; o; o >>= 1) m = fmaxf(m, __shfl_xor_sync(0xffffffffu, m, o));
                float pr4[4]; float sum = 0.f;
#pragma unroll
                for (int i = 0; i < 4; i++) {
                    int s = lane + 32 * i;
                    if (s < DS) { pr4[i] = fex2((es[s] - m) * L2E); sum += pr4[i]; }
                }
#pragma unroll
                for (int o = 16; o; o >>= 1) sum += __shfl_xor_sync(0xffffffffu, sum, o);
                float inv = frcp(sum);
#pragma unroll
                for (int i = 0; i < 4; i++) {
                    int s = lane + 32 * i;
                    if (s < DS) {
                        float a = pr4[i] * inv;
                        es[s] = a;
                        p.out[OFF_C + ((size_t)t * DB + b2) * DS + s] = a;
                        if (t == DT - 1) p.out[OFF_CL + (size_t)b2 * DS + s] = a;
                    }
                }
            }
            __syncthreads();
            for (int e = tid; e < 512; e += NTHR) {
                float acc = 0.f;
                const float* cb = g_ctxbse + (size_t)b2 * DS * DE + e;
#pragma unroll 4
                for (int s = 0; s < DS; s++) acc += es[s] * cb[(size_t)s * DE];
                g_ctxT[pslot(e, b2)] = acc;
            }
            __syncthreads();
            float part = 0.f;
            const float* h1w = g_h1T[wp];
            for (int k = tid; k < 1024; k += NTHR) {
                float v = (k < 512) ? h1w[pslot(k, b2)] : g_ctxT[pslot(k - 512, b2)];
                part += v * p.Wcopy[k];
            }
            red[tid] = part; __syncthreads();
            for (int o = 128; o; o >>= 1) { if (tid < o) red[tid] += red[tid + o]; __syncthreads(); }
            if (tid == 0)
                p.out[OFF_CP + (size_t)t * DB + b2] = sig_f(red[0] + p.bcopy[0]);
        }
        gridbar();
    }

    // ---- epilogue: tail for t=63 + finals ----
    if (bi >= 128 && bi < 144) {
#pragma unroll
        for (int c = 0; c < 8; c++) tacc[c] = 0.f;
        tail_part(tacc, ws, tb, tcg, 0, 128);
        tail_write(tacc, DT - 1, tb, tc0, p.out);
    } else {
        int nb = (bi < 128) ? bi : bi - 16;    // 132 participating blocks
        for (int i = nb * NTHR + tid; i < DB * DH; i += 132 * NTHR) {
            int bb = i >> 9, jx = i & 511;
            int pos = pslot(jx, bb);
            p.out[OFF_HF + i]                 = g_h0T[0][pos];
            p.out[OFF_HF + (size_t)DB*DH + i] = g_h1T[0][pos];
            p.out[OFF_CF + i]                 = g_ctxT[pos];
        }
    }
}

// ---------------------------------------------------------------------------
// host
// ---------------------------------------------------------------------------
static GOp mkop(const float* A, int lda, const float* W, int ldw,
                const float* Ci, int ldci, const float* bias,
                float* C, int ldc, int K) {
    GOp o; o.A = A; o.W = W; o.Ci = Ci; o.bias = bias; o.C = C;
    o.lda = lda; o.ldw = ldw; o.ldci = ldci; o.ldc = ldc; o.K = K;
    return o;
}

extern "C" void kernel_launch(void* const* d_in, const int* in_sizes, int n_in,
                              void* d_out, int out_size) {
    (void)in_sizes; (void)n_in; (void)out_size;
    const int*   inp      = (const int*)  d_in[0];
    const float* hidden   = (const float*)d_in[1];
    const float* context  = (const float*)d_in[2];
    const float* mask     = (const float*)d_in[3];
    const float* init_att = (const float*)d_in[4];
    const float* emb_tab  = (const float*)d_in[5];
    const float* W_ih0    = (const float*)d_in[6];
    const float* W_hh0    = (const float*)d_in[7];
    const float* b_ih0    = (const float*)d_in[8];
    const float* b_hh0    = (const float*)d_in[9];
    const float* W_ih1    = (const float*)d_in[10];
    const float* W_hh1    = (const float*)d_in[11];
    const float* b_ih1    = (const float*)d_in[12];
    const float* b_hh1    = (const float*)d_in[13];
    const float* W_pre    = (const float*)d_in[14];
    const float* b_pre    = (const float*)d_in[15];
    const float* W_q      = (const float*)d_in[16];
    const float* v_att    = (const float*)d_in[17];
    const float* W_copy   = (const float*)d_in[18];
    const float* b_copy   = (const float*)d_in[19];
    const float* W_read   = (const float*)d_in[20];
    const float* b_read   = (const float*)d_in[21];
    float* out = (float*)d_out;

    float *p_emb, *p_gi0e, *p_re, *p_pre, *p_ctxbse;
    cudaGetSymbolAddress((void**)&p_emb,    g_emb);
    cudaGetSymbolAddress((void**)&p_gi0e,   g_gi0e);
    cudaGetSymbolAddress((void**)&p_re,     g_re);
    cudaGetSymbolAddress((void**)&p_pre,    g_pre);
    cudaGetSymbolAddress((void**)&p_ctxbse, g_ctxbse);

    cudaFuncSetAttribute(persist_k, cudaFuncAttributeMaxDynamicSharedMemorySize,
                         SW_TOT * sizeof(float));

    // --- precompute -------------------------------------------------------
    gather_emb_k<<<DT*DB, 128>>>(inp, emb_tab);
    transpose_ctx_k<<<dim3(DS, DB), 128>>>(context);
    init_pack_k<<<128, 256>>>(hidden, init_att);

    {
        GOps g; g.op[0] = mkop(p_emb, DW, W_ih0, DW + DE, nullptr, 0, b_ih0, p_gi0e, G3, DW);
        gemm_k<<<dim3(G3/32, (DT*DB)/64, 1), 128>>>(g);
    }
    {
        GOps g; g.op[0] = mkop(p_emb, DW, W_read, DW + DH + DE, nullptr, 0, b_read, p_re, DH, DW);
        gemm_k<<<dim3(DH/32, (DT*DB)/64, 1), 128>>>(g);
    }
    {
        GOps g; g.op[0] = mkop(p_ctxbse, DE, W_pre, DE, nullptr, 0, b_pre, p_pre, 512, DE);
        gemm_k<<<dim3(512/32, (DB*DS)/64, 1), 128>>>(g);
    }

    // --- persistent recurrent kernel -------------------------------------
    PP pp;
    pp.mask = mask; pp.Wcopy = W_copy; pp.bcopy = b_copy; pp.vatt = v_att;
    pp.W_ih0 = W_ih0; pp.W_hh0 = W_hh0; pp.b_hh0 = b_hh0;
    pp.W_ih1 = W_ih1; pp.W_hh1 = W_hh1; pp.b_ih1 = b_ih1; pp.b_hh1 = b_hh1;
    pp.W_q = W_q; pp.W_read = W_read;
    pp.out = out;
    persist_k<<<GRIDN, NTHR, SW_TOT * sizeof(float)>>>(pp);
}

// round 16
// speedup vs baseline: 1.1757x; 1.0809x over previous
#include <cuda_runtime.h>

// ---------------------------------------------------------------------------
// Problem dims
// ---------------------------------------------------------------------------
#define DT 64
#define DB 64
#define DS 100
#define DH 512
#define DE 512
#define DW 512
#define G3 1536
#define GRIDN 148
#define NTHR 256

// output layout offsets (float elements)
static const size_t OFF_G  = 0;                                  // (T,B,256)
static const size_t OFF_C  = OFF_G  + (size_t)DT*DB*256;         // (T,B,S)
static const size_t OFF_CP = OFF_C  + (size_t)DT*DB*DS;          // (T,B,1)
static const size_t OFF_HF = OFF_CP + (size_t)DT*DB;             // (2,B,H)
static const size_t OFF_CL = OFF_HF + (size_t)2*DB*DH;           // (B,S)
static const size_t OFF_CF = OFF_CL + (size_t)DB*DS;             // (B,E)
static const size_t OFF_GH = OFF_CF + (size_t)DB*DE;             // (T,2,B,H)

// dynamic smem layout (float offsets)
#define SW_A   0        // GRU0: 24 rows x 512
#define SW_C   12288    // GRU1: 24 rows x 512
#define SW_Q   24576    // q:     4 rows x 512
#define SW_R1  26624    // roh:   4 rows x 512
#define SW_SC  28672    // F2 scratch (es 128 + red 256)
#define SW_TOT 29184    // 116736 bytes

// ---------------------------------------------------------------------------
// Device scratch
// ---------------------------------------------------------------------------
__device__ float g_emb   [(size_t)DT*DB*DW];
__device__ float g_gi0e  [(size_t)DT*DB*G3];
__device__ float g_re    [(size_t)DT*DB*DH];
__device__ float g_pre   [(size_t)DB*DS*DE];
__device__ float g_ctxbse[(size_t)DB*DS*DE];
// packed k-major activations: slot(j,b) = (j>>2)*256 + b*4 + (j&3)
__device__ float g_h0T[2][DB*DH];
__device__ float g_h1T[2][DB*DH];
__device__ float g_ctxT  [DB*DE];
__device__ float g_q     [DB*DH];         // NOTE: stores q * 2*log2e
__device__ float g_roh[2][DB*DH];
__device__ float g_energy[DB*DS];

// grid barrier state (monotone; replay-safe) — separate cache lines
__device__ __align__(128) unsigned long long g_arrive = 0ULL;
__device__ __align__(128) unsigned long long g_epoch  = 0ULL;

// ---------------------------------------------------------------------------
// fast math
// ---------------------------------------------------------------------------
typedef unsigned long long ull;

__device__ __forceinline__ float fex2(float x){ float y; asm("ex2.approx.f32 %0, %1;" : "=f"(y) : "f"(x)); return y; }
__device__ __forceinline__ float frcp(float x){ float y; asm("rcp.approx.f32 %0, %1;" : "=f"(y) : "f"(x)); return y; }
#define L2E 1.4426950408889634f

__device__ __forceinline__ float tanh_f(float x){
    float xc = fminf(fmaxf(x, -15.f), 15.f);
    float t  = fex2(xc * (2.f * L2E));
    return (t - 1.f) * frcp(t + 1.f);
}
__device__ __forceinline__ float sig_f(float x){
    float xc = fminf(fmaxf(x, -30.f), 30.f);
    return frcp(1.f + fex2(-xc * L2E));
}

__device__ __forceinline__ int pslot(int j, int b){ return ((j >> 2) << 8) + (b << 2) + (j & 3); }

// packed f32x2 ops
__device__ __forceinline__ ull add2(ull a, ull b){ ull d; asm("add.rn.f32x2 %0,%1,%2;" : "=l"(d) : "l"(a), "l"(b)); return d; }
__device__ __forceinline__ ull mul2(ull a, ull b){ ull d; asm("mul.rn.f32x2 %0,%1,%2;" : "=l"(d) : "l"(a), "l"(b)); return d; }
__device__ __forceinline__ ull fma2(ull a, ull b, ull c){ ull d; asm("fma.rn.f32x2 %0,%1,%2,%3;" : "=l"(d) : "l"(a), "l"(b), "l"(c)); return d; }
__device__ __forceinline__ ull pack2(float lo, float hi){ ull d; asm("mov.b64 %0,{%1,%2};" : "=l"(d) : "f"(lo), "f"(hi)); return d; }
__device__ __forceinline__ void unpack2(ull v, float& lo, float& hi){ asm("mov.b64 {%0,%1},%2;" : "=f"(lo), "=f"(hi) : "l"(v)); }

__device__ __forceinline__ float hsum4(ull a, ull b){
    float al, ah, bl, bh;
    unpack2(a, al, ah); unpack2(b, bl, bh);
    return (al + ah) + (bl + bh);
}

// packed tanh-dot step: acc += v2 * tanh(pre2 + q)  where qk2 = q*2L2E, pre scaled by K2
__device__ __forceinline__ ull tanh_acc(ull pre2, ull qk2, ull v2, ull acc,
                                        ull K2, ull ONE2, ull TWO2, ull NEG12) {
    ull xh = fma2(pre2, K2, qk2);           // 2x*log2e (packed)
    float xl, xhh; unpack2(xh, xl, xhh);
    float tl = fex2(xl), th = fex2(xhh);    // e^{2x}
    ull t2 = pack2(tl, th);
    ull y2 = add2(t2, ONE2);                // t+1 (>= 1)
    float yl, yh; unpack2(y2, yl, yh);
    ull r2 = pack2(__int_as_float(0x7EF311C3 - __float_as_int(yl)),
                   __int_as_float(0x7EF311C3 - __float_as_int(yh)));
    ull ny = mul2(y2, NEG12);
    ull u  = fma2(ny, r2, TWO2); r2 = mul2(r2, u);
    u      = fma2(ny, r2, TWO2); r2 = mul2(r2, u);   // ~1e-7 rcp(t+1)
    ull num = add2(t2, NEG12);              // t-1
    return fma2(v2, mul2(num, r2), acc);
}

// ---------------------------------------------------------------------------
// grid barrier
// ---------------------------------------------------------------------------
__device__ __forceinline__ ull ld_acq(const ull* p){
    ull v; asm volatile("ld.acquire.gpu.u64 %0, [%1];" : "=l"(v) : "l"(p)); return v;
}

__device__ __forceinline__ void gridbar() {
    __syncthreads();
    if (threadIdx.x == 0) {
        __threadfence();
        unsigned long long old = atomicAdd(&g_arrive, 1ULL);
        unsigned long long target = old / GRIDN + 1ULL;
        if (old % GRIDN == GRIDN - 1) {
            atomicAdd(&g_epoch, 1ULL);
        } else {
            while (ld_acq(&g_epoch) < target) { }
        }
    }
    __syncthreads();
}

// ---------------------------------------------------------------------------
// fp32 tiled GEMM for precompute (proven)
// ---------------------------------------------------------------------------
struct GOp {
    const float* A; const float* W; const float* Ci; const float* bias;
    float* C;
    int lda, ldw, ldci, ldc, K;
};
struct GOps { GOp op[8]; };

__global__ void __launch_bounds__(128) gemm_k(GOps ops) {
    GOp op = ops.op[blockIdx.z];
    __shared__ __align__(16) float As[16][64];
    __shared__ __align__(16) float Ws[16][32];
    int tid = threadIdx.x;
    int tx = tid & 15, ty = tid >> 4;
    int m0 = blockIdx.y << 6, n0 = blockIdx.x << 5;
    int arow = tid >> 1, akh = (tid & 1) << 3;
    const float* Ap = op.A + (size_t)(m0 + arow) * op.lda + akh;
    int wrow = (tid & 63) >> 1, wkh = (tid & 1) << 3;
    const float* Wp = op.W + (size_t)(n0 + wrow) * op.ldw + wkh;
    bool wload = (tid < 64);
    float acc[16];
#pragma unroll
    for (int i = 0; i < 16; i++) acc[i] = 0.f;
    for (int k0 = 0; k0 < op.K; k0 += 16) {
        float4 a0 = *(const float4*)(Ap + k0);
        float4 a1 = *(const float4*)(Ap + k0 + 4);
        As[akh+0][arow] = a0.x; As[akh+1][arow] = a0.y;
        As[akh+2][arow] = a0.z; As[akh+3][arow] = a0.w;
        As[akh+4][arow] = a1.x; As[akh+5][arow] = a1.y;
        As[akh+6][arow] = a1.z; As[akh+7][arow] = a1.w;
        if (wload) {
            float4 w0 = *(const float4*)(Wp + k0);
            float4 w1 = *(const float4*)(Wp + k0 + 4);
            Ws[wkh+0][wrow] = w0.x; Ws[wkh+1][wrow] = w0.y;
            Ws[wkh+2][wrow] = w0.z; Ws[wkh+3][wrow] = w0.w;
            Ws[wkh+4][wrow] = w1.x; Ws[wkh+5][wrow] = w1.y;
            Ws[wkh+6][wrow] = w1.z; Ws[wkh+7][wrow] = w1.w;
        }
        __syncthreads();
#pragma unroll
        for (int k = 0; k < 16; k++) {
            float4 av = *(const float4*)&As[k][tx << 2];
            float4 wv = *(const float4*)&Ws[k][ty << 2];
            float a[4] = {av.x, av.y, av.z, av.w};
            float w[4] = {wv.x, wv.y, wv.z, wv.w};
#pragma unroll
            for (int i = 0; i < 4; i++)
#pragma unroll
                for (int j = 0; j < 4; j++)
                    acc[i*4+j] += a[i] * w[j];
        }
        __syncthreads();
    }
    int nb = n0 + (ty << 2);
#pragma unroll
    for (int i = 0; i < 4; i++) {
        int m = m0 + (tx << 2) + i;
        float v[4];
#pragma unroll
        for (int j = 0; j < 4; j++) {
            float c = acc[i*4+j];
            if (op.Ci)   c += op.Ci[(size_t)m * op.ldci + nb + j];
            if (op.bias) c += op.bias[nb + j];
            v[j] = c;
        }
        float4 o = {v[0], v[1], v[2], v[3]};
        *(float4*)&op.C[(size_t)m * op.ldc + nb] = o;
    }
}

// ---------------------------------------------------------------------------
// precompute helpers
// ---------------------------------------------------------------------------
__global__ void gather_emb_k(const int* __restrict__ inp, const float* __restrict__ tab) {
    int tb = blockIdx.x;
    int idx = inp[tb];
    const float4* src = (const float4*)(tab + (size_t)idx * DW);
    float4* dst = (float4*)(g_emb + (size_t)tb * DW);
    dst[threadIdx.x] = src[threadIdx.x];
}

__global__ void transpose_ctx_k(const float* __restrict__ ctx) {
    int s = blockIdx.x, b = blockIdx.y;
    float4 v = ((const float4*)(ctx + ((size_t)s * DB + b) * DE))[threadIdx.x];
    ((float4*)(g_ctxbse + ((size_t)b * DS + s) * DE))[threadIdx.x] = v;
}

// ---------------------------------------------------------------------------
// persistent decoder
// ---------------------------------------------------------------------------
struct PP {
    const float* mask; const float* Wcopy; const float* bcopy; const float* vatt;
    const float* W_ih0; const float* W_hh0; const float* b_hh0;
    const float* W_ih1; const float* W_hh1; const float* b_ih1; const float* b_hh1;
    const float* W_q;   const float* W_read;
    const float* hidden; const float* init_att;
    float* out;
};

// GRU with resident weights, f32x2 packed inner loop.
__device__ __forceinline__ void gru_do(
    const float* __restrict__ w, int b, int jj, int j,
    const float* __restrict__ xp, const float* __restrict__ hp, float* __restrict__ hop,
    float bxr, float bxz, float bxn, float bhr, float bhz, float bhn,
    float* __restrict__ outGH)
{
    const float* wxr = w + jj * 512;
    const float* wxz = wxr + 2048;
    const float* wxn = wxr + 4096;
    const float* whr = w + (12 + jj) * 512;
    const float* whz = whr + 2048;
    const float* whn = whr + 4096;
    ull ar0=0,ar1=0, az0=0,az1=0, an0=0,an1=0;
    ull hr0=0,hr1=0, hz0=0,hz1=0, hn0=0,hn1=0;
#pragma unroll 4
    for (int k4 = 0; k4 < 128; k4++) {
        ulonglong2 a = *(const ulonglong2*)(xp + k4 * 256 + b * 4);
        ulonglong2 h = *(const ulonglong2*)(hp + k4 * 256 + b * 4);
        ulonglong2 wv;
        wv = *(const ulonglong2*)(wxr + k4 * 4); ar0 = fma2(a.x, wv.x, ar0); ar1 = fma2(a.y, wv.y, ar1);
        wv = *(const ulonglong2*)(wxz + k4 * 4); az0 = fma2(a.x, wv.x, az0); az1 = fma2(a.y, wv.y, az1);
        wv = *(const ulonglong2*)(wxn + k4 * 4); an0 = fma2(a.x, wv.x, an0); an1 = fma2(a.y, wv.y, an1);
        wv = *(const ulonglong2*)(whr + k4 * 4); hr0 = fma2(h.x, wv.x, hr0); hr1 = fma2(h.y, wv.y, hr1);
        wv = *(const ulonglong2*)(whz + k4 * 4); hz0 = fma2(h.x, wv.x, hz0); hz1 = fma2(h.y, wv.y, hz1);
        wv = *(const ulonglong2*)(whn + k4 * 4); hn0 = fma2(h.x, wv.x, hn0); hn1 = fma2(h.y, wv.y, hn1);
    }
    float air = bxr + hsum4(ar0, ar1);
    float aiz = bxz + hsum4(az0, az1);
    float ain = bxn + hsum4(an0, an1);
    float ahr = bhr + hsum4(hr0, hr1);
    float ahz = bhz + hsum4(hz0, hz1);
    float ahn = bhn + hsum4(hn0, hn1);
    float r  = sig_f(air + ahr);
    float z  = sig_f(aiz + ahz);
    float n  = tanh_f(ain + r * ahn);
    float hprev = hp[pslot(j, b)];
    float hnew  = (1.f - z) * n + z * hprev;
    hop[pslot(j, b)] = hnew;
    outGH[b * 512 + j] = hnew;
}

// readout-ctx partial (blocks 128..143)
__device__ __forceinline__ void tail_part(float* acc, const float* __restrict__ wrc,
                                          int tb, int tcg, int e4lo, int e4hi) {
#pragma unroll 2
    for (int e4 = e4lo; e4 < e4hi; e4++) {
        float4 a = *(const float4*)(g_ctxT + e4 * 256 + tb * 4);
#pragma unroll
        for (int c = 0; c < 8; c++) {
            float4 w = *(const float4*)(wrc + (tcg * 8 + c) * 512 + e4 * 4);
            acc[c] += a.x*w.x + a.y*w.y + a.z*w.z + a.w*w.w;
        }
    }
}

__device__ __forceinline__ void tail_write(const float* acc, int tt, int tb, int tc0,
                                           float* __restrict__ out) {
    const float* re = g_re + ((size_t)tt * DB + tb) * DH + tc0;
    const float* rh = g_roh[tt & 1] + (size_t)tb * DH + tc0;
#pragma unroll
    for (int p = 0; p < 4; p++) {
        float v0 = acc[2*p]     + re[2*p]     + rh[2*p];
        float v1 = acc[2*p + 1] + re[2*p + 1] + rh[2*p + 1];
        out[OFF_G + ((size_t)tt * DB + tb) * 256 + ((tc0 >> 1) + p)] = fmaxf(v0, v1);
    }
}

extern __shared__ float ws[];

__global__ void __launch_bounds__(NTHR, 1) persist_k(PP p) {
    int tid = threadIdx.x, bi = blockIdx.x;
    int b = tid & 63, jj = tid >> 6;

    // ---- prologue: weight residency + state init ----
    if (bi < 128) {
        int j0 = bi * 4;
        for (int i = tid; i < 24 * 128; i += NTHR) {          // GRU0
            int r = i >> 7, k4 = (i & 127) << 2;
            const float* src = (r < 12)
                ? p.W_ih0 + (size_t)((r >> 2) * 512 + j0 + (r & 3)) * 1024 + 512 + k4
                : p.W_hh0 + (size_t)((((r - 12) >> 2)) * 512 + j0 + ((r - 12) & 3)) * 512 + k4;
            *(float4*)(ws + SW_A + r * 512 + k4) = *(const float4*)src;
        }
        for (int i = tid; i < 24 * 128; i += NTHR) {          // GRU1
            int r = i >> 7, k4 = (i & 127) << 2;
            const float* src = (r < 12)
                ? p.W_ih1 + (size_t)((r >> 2) * 512 + j0 + (r & 3)) * 512 + k4
                : p.W_hh1 + (size_t)((((r - 12) >> 2)) * 512 + j0 + ((r - 12) & 3)) * 512 + k4;
            *(float4*)(ws + SW_C + r * 512 + k4) = *(const float4*)src;
        }
        for (int i = tid; i < 4 * 128; i += NTHR) {           // q rows
            int r = i >> 7, k4 = (i & 127) << 2;
            *(float4*)(ws + SW_Q + r * 512 + k4) =
                *(const float4*)(p.W_q + (size_t)(j0 + r) * 512 + k4);
        }
        for (int i = tid; i < 4 * 128; i += NTHR) {           // roh rows
            int r = i >> 7, k4 = (i & 127) << 2;
            *(float4*)(ws + SW_R1 + r * 512 + k4) =
                *(const float4*)(p.W_read + (size_t)(j0 + r) * G3 + 512 + k4);
        }
    } else if (bi < 144) {
        int c0 = (bi - 128) * 32;
        for (int i = tid; i < 32 * 128; i += NTHR) {          // readout-ctx rows
            int r = i >> 7, k4 = (i & 127) << 2;
            *(float4*)(ws + r * 512 + k4) =
                *(const float4*)(p.W_read + (size_t)(c0 + r) * G3 + 1024 + k4);
        }
    } else {
        // blocks 144..147: pack initial state
        for (int i = (bi - 144) * NTHR + tid; i < DB * DH; i += 4 * NTHR) {
            int bb = i >> 9, jx = i & 511;
            int pos = pslot(jx, bb);
            g_h0T[0][pos] = p.hidden[i];
            g_h1T[0][pos] = p.hidden[(size_t)DB*DH + i];
            g_ctxT[pos]   = p.init_att[i];
        }
    }
    gridbar();   // init state visible to all

    int j = bi * 4 + jj;
    float b0r=0,b0z=0,b0n=0, b1ir=0,b1iz=0,b1in=0, b1hr=0,b1hz=0,b1hn=0;
    if (bi < 128) {
        b0r  = p.b_hh0[j];  b0z  = p.b_hh0[j + 512];  b0n  = p.b_hh0[j + 1024];
        b1ir = p.b_ih1[j];  b1iz = p.b_ih1[j + 512];  b1in = p.b_ih1[j + 1024];
        b1hr = p.b_hh1[j];  b1hz = p.b_hh1[j + 512];  b1hn = p.b_hh1[j + 1024];
    }
    int tb = tid & 63, tcg = tid >> 6;
    int tc0 = (bi - 128) * 32 + tcg * 8;
    float tacc[8];

    const ull K2    = pack2(2.f*L2E, 2.f*L2E);
    const ull ONE2  = pack2(1.f, 1.f);
    const ull TWO2  = pack2(2.f, 2.f);
    const ull NEG12 = pack2(-1.f, -1.f);

    for (int t = 0; t < DT; t++) {
        int rp = t & 1, wp = rp ^ 1;

        // ---- A: GRU0 || tail-part1(t-1) ----
        if (bi < 128) {
            const float* giB = g_gi0e + ((size_t)t * DB + b) * G3;
            gru_do(ws + SW_A, b, jj, j, g_ctxT, g_h0T[rp], g_h0T[wp],
                   giB[j], giB[j + 512], giB[j + 1024], b0r, b0z, b0n,
                   p.out + OFF_GH + ((size_t)t * 2 + 0) * (DB * DH));
        } else if (bi < 144 && t > 0) {
#pragma unroll
            for (int c = 0; c < 8; c++) tacc[c] = 0.f;
            tail_part(tacc, ws, tb, tcg, 0, 64);
        }
        gridbar();

        // ---- C: GRU1 || tail-part2(t-1) ----
        if (bi < 128) {
            gru_do(ws + SW_C, b, jj, j, g_h0T[wp], g_h1T[rp], g_h1T[wp],
                   b1ir, b1iz, b1in, b1hr, b1hz, b1hn,
                   p.out + OFF_GH + ((size_t)t * 2 + 1) * (DB * DH));
        } else if (bi < 144 && t > 0) {
            tail_part(tacc, ws, tb, tcg, 64, 128);
        }
        gridbar();

        // ---- E: q(scaled) + roh || tail-write(t-1) ----
        if (bi < 128) {
            const float* h1w = g_h1T[wp];
            const float* wq = ws + SW_Q  + jj * 512;
            const float* wr = ws + SW_R1 + jj * 512;
            ull q0=0,q1=0, r0=0,r1=0;
#pragma unroll 4
            for (int k4 = 0; k4 < 128; k4++) {
                ulonglong2 a = *(const ulonglong2*)(h1w + k4 * 256 + b * 4);
                ulonglong2 x = *(const ulonglong2*)(wq + k4 * 4);
                q0 = fma2(a.x, x.x, q0); q1 = fma2(a.y, x.y, q1);
                ulonglong2 y = *(const ulonglong2*)(wr + k4 * 4);
                r0 = fma2(a.x, y.x, r0); r1 = fma2(a.y, y.y, r1);
            }
            g_q[b * 512 + j] = hsum4(q0, q1) * (2.f * L2E);   // pre-scaled for F1
            g_roh[t & 1][b * 512 + j] = hsum4(r0, r1);
        } else if (bi < 144 && t > 0) {
            tail_write(tacc, t - 1, tb, tc0, p.out);
        }
        gridbar();

        // ---- F1: attention energies (all blocks; packed tanh) ----
        {
            int gw = bi * 8 + (tid >> 5), lane = tid & 31;
            for (int idx = gw; idx < DB * DS; idx += GRIDN * 8) {
                int bb = idx / DS;
                const float* pr = g_pre + (size_t)idx * 512;
                const float* qq = g_q + (size_t)bb * 512;
                ull acc0 = 0, acc1 = 0;
#pragma unroll
                for (int i4 = 0; i4 < 4; i4++) {
                    int a0i = i4 * 128 + lane * 4;
                    ulonglong2 pv = *(const ulonglong2*)(pr + a0i);
                    ulonglong2 qv = *(const ulonglong2*)(qq + a0i);
                    ulonglong2 vv = *(const ulonglong2*)(p.vatt + a0i);
                    acc0 = tanh_acc(pv.x, qv.x, vv.x, acc0, K2, ONE2, TWO2, NEG12);
                    acc1 = tanh_acc(pv.y, qv.y, vv.y, acc1, K2, ONE2, TWO2, NEG12);
                }
                float acc = hsum4(acc0, acc1);
#pragma unroll
                for (int o = 16; o; o >>= 1) acc += __shfl_down_sync(0xffffffffu, acc, o);
                if (lane == 0)
                    g_energy[idx] = (p.mask[idx] > 0.5f) ? -1e18f : acc;
            }
        }
        gridbar();

        // ---- F2: softmax + context + copy (blocks 0..63) ----
        if (bi < DB) {
            int b2 = bi;
            float* es  = ws + SW_SC;
            float* red = ws + SW_SC + 128;
            for (int s = tid; s < DS; s += NTHR) es[s] = g_energy[b2 * DS + s];
            __syncthreads();
            if (tid < 32) {
                int lane = tid;
                float m = -3.4e38f;
#pragma unroll
                for (int i = 0; i < 4; i++) { int s = lane + 32 * i; if (s < DS) m = fmaxf(m, es[s]); }
#pragma unroll
                for (int o = 16; o; o >>= 1) m = fmaxf(m, __shfl_xor_sync(0xffffffffu, m, o));
                float pr4[4]; float sum = 0.f;
#pragma unroll
                for (int i = 0; i < 4; i++) {
                    int s = lane + 32 * i;
                    if (s < DS) { pr4[i] = fex2((es[s] - m) * L2E); sum += pr4[i]; }
                }
#pragma unroll
                for (int o = 16; o; o >>= 1) sum += __shfl_xor_sync(0xffffffffu, sum, o);
                float inv = frcp(sum);
#pragma unroll
                for (int i = 0; i < 4; i++) {
                    int s = lane + 32 * i;
                    if (s < DS) {
                        float a = pr4[i] * inv;
                        es[s] = a;
                        p.out[OFF_C + ((size_t)t * DB + b2) * DS + s] = a;
                        if (t == DT - 1) p.out[OFF_CL + (size_t)b2 * DS + s] = a;
                    }
                }
            }
            __syncthreads();
            for (int e = tid; e < 512; e += NTHR) {
                float acc = 0.f;
                const float* cb = g_ctxbse + (size_t)b2 * DS * DE + e;
#pragma unroll 4
                for (int s = 0; s < DS; s++) acc += es[s] * cb[(size_t)s * DE];
                g_ctxT[pslot(e, b2)] = acc;
            }
            __syncthreads();
            float part = 0.f;
            const float* h1w = g_h1T[wp];
            for (int k = tid; k < 1024; k += NTHR) {
                float v = (k < 512) ? h1w[pslot(k, b2)] : g_ctxT[pslot(k - 512, b2)];
                part += v * p.Wcopy[k];
            }
            red[tid] = part; __syncthreads();
            for (int o = 128; o; o >>= 1) { if (tid < o) red[tid] += red[tid + o]; __syncthreads(); }
            if (tid == 0)
                p.out[OFF_CP + (size_t)t * DB + b2] = sig_f(red[0] + p.bcopy[0]);
        }
        gridbar();
    }

    // ---- epilogue: tail for t=63 + finals ----
    if (bi >= 128 && bi < 144) {
#pragma unroll
        for (int c = 0; c < 8; c++) tacc[c] = 0.f;
        tail_part(tacc, ws, tb, tcg, 0, 128);
        tail_write(tacc, DT - 1, tb, tc0, p.out);
    } else {
        int nb = (bi < 128) ? bi : bi - 16;    // 132 participating blocks
        for (int i = nb * NTHR + tid; i < DB * DH; i += 132 * NTHR) {
            int bb = i >> 9, jx = i & 511;
            int pos = pslot(jx, bb);
            p.out[OFF_HF + i]                 = g_h0T[0][pos];
            p.out[OFF_HF + (size_t)DB*DH + i] = g_h1T[0][pos];
            p.out[OFF_CF + i]                 = g_ctxT[pos];
        }
    }
}

// ---------------------------------------------------------------------------
// host
// ---------------------------------------------------------------------------
static GOp mkop(const float* A, int lda, const float* W, int ldw,
                const float* Ci, int ldci, const float* bias,
                float* C, int ldc, int K) {
    GOp o; o.A = A; o.W = W; o.Ci = Ci; o.bias = bias; o.C = C;
    o.lda = lda; o.ldw = ldw; o.ldci = ldci; o.ldc = ldc; o.K = K;
    return o;
}

extern "C" void kernel_launch(void* const* d_in, const int* in_sizes, int n_in,
                              void* d_out, int out_size) {
    (void)in_sizes; (void)n_in; (void)out_size;
    const int*   inp      = (const int*)  d_in[0];
    const float* hidden   = (const float*)d_in[1];
    const float* context  = (const float*)d_in[2];
    const float* mask     = (const float*)d_in[3];
    const float* init_att = (const float*)d_in[4];
    const float* emb_tab  = (const float*)d_in[5];
    const float* W_ih0    = (const float*)d_in[6];
    const float* W_hh0    = (const float*)d_in[7];
    const float* b_ih0    = (const float*)d_in[8];
    const float* b_hh0    = (const float*)d_in[9];
    const float* W_ih1    = (const float*)d_in[10];
    const float* W_hh1    = (const float*)d_in[11];
    const float* b_ih1    = (const float*)d_in[12];
    const float* b_hh1    = (const float*)d_in[13];
    const float* W_pre    = (const float*)d_in[14];
    const float* b_pre    = (const float*)d_in[15];
    const float* W_q      = (const float*)d_in[16];
    const float* v_att    = (const float*)d_in[17];
    const float* W_copy   = (const float*)d_in[18];
    const float* b_copy   = (const float*)d_in[19];
    const float* W_read   = (const float*)d_in[20];
    const float* b_read   = (const float*)d_in[21];
    float* out = (float*)d_out;

    float *p_emb, *p_gi0e, *p_re, *p_pre, *p_ctxbse;
    cudaGetSymbolAddress((void**)&p_emb,    g_emb);
    cudaGetSymbolAddress((void**)&p_gi0e,   g_gi0e);
    cudaGetSymbolAddress((void**)&p_re,     g_re);
    cudaGetSymbolAddress((void**)&p_pre,    g_pre);
    cudaGetSymbolAddress((void**)&p_ctxbse, g_ctxbse);

    cudaFuncSetAttribute(persist_k, cudaFuncAttributeMaxDynamicSharedMemorySize,
                         SW_TOT * sizeof(float));

    // launches ordered so persist_k is launch index 5 (ncu -s 5 -c 1 captures it)
    gather_emb_k<<<DT*DB, 128>>>(inp, emb_tab);                    // 0
    transpose_ctx_k<<<dim3(DS, DB), 128>>>(context);               // 1

    {
        GOps g; g.op[0] = mkop(p_emb, DW, W_ih0, DW + DE, nullptr, 0, b_ih0, p_gi0e, G3, DW);
        gemm_k<<<dim3(G3/32, (DT*DB)/64, 1), 128>>>(g);            // 2
    }
    {
        GOps g; g.op[0] = mkop(p_emb, DW, W_read, DW + DH + DE, nullptr, 0, b_read, p_re, DH, DW);
        gemm_k<<<dim3(DH/32, (DT*DB)/64, 1), 128>>>(g);            // 3
    }
    {
        GOps g; g.op[0] = mkop(p_ctxbse, DE, W_pre, DE, nullptr, 0, b_pre, p_pre, 512, DE);
        gemm_k<<<dim3(512/32, (DB*DS)/64, 1), 128>>>(g);           // 4
    }

    PP pp;
    pp.mask = mask; pp.Wcopy = W_copy; pp.bcopy = b_copy; pp.vatt = v_att;
    pp.W_ih0 = W_ih0; pp.W_hh0 = W_hh0; pp.b_hh0 = b_hh0;
    pp.W_ih1 = W_ih1; pp.W_hh1 = W_hh1; pp.b_ih1 = b_ih1; pp.b_hh1 = b_hh1;
    pp.W_q = W_q; pp.W_read = W_read;
    pp.hidden = hidden; pp.init_att = init_att;
    pp.out = out;
    persist_k<<<GRIDN, NTHR, SW_TOT * sizeof(float)>>>(pp);        // 5
}

// round 17
// speedup vs baseline: 1.6525x; 1.4055x over previous
#include <cuda_runtime.h>

// ---------------------------------------------------------------------------
// Problem dims
// ---------------------------------------------------------------------------
#define DT 64
#define DB 64
#define DS 100
#define DH 512
#define DE 512
#define DW 512
#define G3 1536
#define GRIDN 148
#define NTHR 1024

// output layout offsets (float elements)
static const size_t OFF_G  = 0;                                  // (T,B,256)
static const size_t OFF_C  = OFF_G  + (size_t)DT*DB*256;         // (T,B,S)
static const size_t OFF_CP = OFF_C  + (size_t)DT*DB*DS;          // (T,B,1)
static const size_t OFF_HF = OFF_CP + (size_t)DT*DB;             // (2,B,H)
static const size_t OFF_CL = OFF_HF + (size_t)2*DB*DH;           // (B,S)
static const size_t OFF_CF = OFF_CL + (size_t)DB*DS;             // (B,E)
static const size_t OFF_GH = OFF_CF + (size_t)DB*DE;             // (T,2,B,H)

// dynamic smem layout (float offsets)
#define SW_A    0        // GRU0: 24 rows x 512
#define SW_C    12288    // GRU1: 24 rows x 512
#define SW_Q    24576    // q:     4 rows x 512
#define SW_R1   26624    // roh:   4 rows x 512
#define SW_RED  28672    // reduction buffer: 256*4*6 floats
#define SW_SC   34816    // F2 es[128]
#define SW_TOT  34944    // 139776 bytes

// ---------------------------------------------------------------------------
// Device scratch
// ---------------------------------------------------------------------------
__device__ float g_emb   [(size_t)DT*DB*DW];
__device__ float g_gi0e  [(size_t)DT*DB*G3];
__device__ float g_re    [(size_t)DT*DB*DH];
__device__ float g_pre   [(size_t)DB*DS*DE];
__device__ float g_ctxbse[(size_t)DB*DS*DE];
// packed k-major activations: slot(j,b) = (j>>2)*256 + b*4 + (j&3)
__device__ float g_h0T[2][DB*DH];
__device__ float g_h1T[2][DB*DH];
__device__ float g_ctxT  [DB*DE];
__device__ float g_q     [DB*DH];         // stores q * 2*log2e
__device__ float g_roh[2][DB*DH];
__device__ float g_energy[DB*DS];

__device__ __align__(128) unsigned long long g_arrive = 0ULL;
__device__ __align__(128) unsigned long long g_epoch  = 0ULL;

// ---------------------------------------------------------------------------
// fast math
// ---------------------------------------------------------------------------
typedef unsigned long long ull;

__device__ __forceinline__ float fex2(float x){ float y; asm("ex2.approx.f32 %0, %1;" : "=f"(y) : "f"(x)); return y; }
__device__ __forceinline__ float frcp(float x){ float y; asm("rcp.approx.f32 %0, %1;" : "=f"(y) : "f"(x)); return y; }
#define L2E 1.4426950408889634f

__device__ __forceinline__ float tanh_f(float x){
    float xc = fminf(fmaxf(x, -15.f), 15.f);
    float t  = fex2(xc * (2.f * L2E));
    return (t - 1.f) * frcp(t + 1.f);
}
__device__ __forceinline__ float sig_f(float x){
    float xc = fminf(fmaxf(x, -30.f), 30.f);
    return frcp(1.f + fex2(-xc * L2E));
}

__device__ __forceinline__ int pslot(int j, int b){ return ((j >> 2) << 8) + (b << 2) + (j & 3); }

// packed f32x2 ops
__device__ __forceinline__ ull add2(ull a, ull b){ ull d; asm("add.rn.f32x2 %0,%1,%2;" : "=l"(d) : "l"(a), "l"(b)); return d; }
__device__ __forceinline__ ull mul2(ull a, ull b){ ull d; asm("mul.rn.f32x2 %0,%1,%2;" : "=l"(d) : "l"(a), "l"(b)); return d; }
__device__ __forceinline__ ull fma2(ull a, ull b, ull c){ ull d; asm("fma.rn.f32x2 %0,%1,%2,%3;" : "=l"(d) : "l"(a), "l"(b), "l"(c)); return d; }
__device__ __forceinline__ ull pack2(float lo, float hi){ ull d; asm("mov.b64 %0,{%1,%2};" : "=l"(d) : "f"(lo), "f"(hi)); return d; }
__device__ __forceinline__ void unpack2(ull v, float& lo, float& hi){ asm("mov.b64 {%0,%1},%2;" : "=f"(lo), "=f"(hi) : "l"(v)); }

__device__ __forceinline__ float hsum4(ull a, ull b){
    float al, ah, bl, bh;
    unpack2(a, al, ah); unpack2(b, bl, bh);
    return (al + ah) + (bl + bh);
}

// packed tanh-dot: acc += v2 * tanh(pre2 + q) ; qk2 pre-scaled by 2log2e, pre scaled by K2
__device__ __forceinline__ ull tanh_acc(ull pre2, ull qk2, ull v2, ull acc,
                                        ull K2, ull ONE2, ull TWO2, ull NEG12) {
    ull xh = fma2(pre2, K2, qk2);
    float xl, xhh; unpack2(xh, xl, xhh);
    float tl = fex2(xl), th = fex2(xhh);
    ull t2 = pack2(tl, th);
    ull y2 = add2(t2, ONE2);
    float yl, yh; unpack2(y2, yl, yh);
    ull r2 = pack2(__int_as_float(0x7EF311C3 - __float_as_int(yl)),
                   __int_as_float(0x7EF311C3 - __float_as_int(yh)));
    ull ny = mul2(y2, NEG12);
    ull u  = fma2(ny, r2, TWO2); r2 = mul2(r2, u);
    u      = fma2(ny, r2, TWO2); r2 = mul2(r2, u);
    ull num = add2(t2, NEG12);
    return fma2(v2, mul2(num, r2), acc);
}

// ---------------------------------------------------------------------------
// grid barrier
// ---------------------------------------------------------------------------
__device__ __forceinline__ ull ld_acq(const ull* p){
    ull v; asm volatile("ld.acquire.gpu.u64 %0, [%1];" : "=l"(v) : "l"(p)); return v;
}

__device__ __forceinline__ void gridbar() {
    __syncthreads();
    if (threadIdx.x == 0) {
        __threadfence();
        unsigned long long old = atomicAdd(&g_arrive, 1ULL);
        unsigned long long target = old / GRIDN + 1ULL;
        if (old % GRIDN == GRIDN - 1) {
            atomicAdd(&g_epoch, 1ULL);
        } else {
            while (ld_acq(&g_epoch) < target) { }
        }
    }
    __syncthreads();
}

// ---------------------------------------------------------------------------
// fp32 tiled GEMM for precompute — inner loop in f32x2
// ---------------------------------------------------------------------------
struct GOp {
    const float* A; const float* W; const float* Ci; const float* bias;
    float* C;
    int lda, ldw, ldci, ldc, K;
};
struct GOps { GOp op[8]; };

__global__ void __launch_bounds__(128) gemm_k(GOps ops) {
    GOp op = ops.op[blockIdx.z];
    __shared__ __align__(16) float As[16][64];
    __shared__ __align__(16) float Ws[16][32];
    int tid = threadIdx.x;
    int tx = tid & 15, ty = tid >> 4;
    int m0 = blockIdx.y << 6, n0 = blockIdx.x << 5;
    int arow = tid >> 1, akh = (tid & 1) << 3;
    const float* Ap = op.A + (size_t)(m0 + arow) * op.lda + akh;
    int wrow = (tid & 63) >> 1, wkh = (tid & 1) << 3;
    const float* Wp = op.W + (size_t)(n0 + wrow) * op.ldw + wkh;
    bool wload = (tid < 64);
    ull acc2[8];
#pragma unroll
    for (int i = 0; i < 8; i++) acc2[i] = pack2(0.f, 0.f);
    for (int k0 = 0; k0 < op.K; k0 += 16) {
        float4 a0 = *(const float4*)(Ap + k0);
        float4 a1 = *(const float4*)(Ap + k0 + 4);
        As[akh+0][arow] = a0.x; As[akh+1][arow] = a0.y;
        As[akh+2][arow] = a0.z; As[akh+3][arow] = a0.w;
        As[akh+4][arow] = a1.x; As[akh+5][arow] = a1.y;
        As[akh+6][arow] = a1.z; As[akh+7][arow] = a1.w;
        if (wload) {
            float4 w0 = *(const float4*)(Wp + k0);
            float4 w1 = *(const float4*)(Wp + k0 + 4);
            Ws[wkh+0][wrow] = w0.x; Ws[wkh+1][wrow] = w0.y;
            Ws[wkh+2][wrow] = w0.z; Ws[wkh+3][wrow] = w0.w;
            Ws[wkh+4][wrow] = w1.x; Ws[wkh+5][wrow] = w1.y;
            Ws[wkh+6][wrow] = w1.z; Ws[wkh+7][wrow] = w1.w;
        }
        __syncthreads();
#pragma unroll
        for (int k = 0; k < 16; k++) {
            float4 av = *(const float4*)&As[k][tx << 2];
            ulonglong2 wv = *(const ulonglong2*)&Ws[k][ty << 2];
            ull a;
            a = pack2(av.x, av.x); acc2[0] = fma2(a, wv.x, acc2[0]); acc2[1] = fma2(a, wv.y, acc2[1]);
            a = pack2(av.y, av.y); acc2[2] = fma2(a, wv.x, acc2[2]); acc2[3] = fma2(a, wv.y, acc2[3]);
            a = pack2(av.z, av.z); acc2[4] = fma2(a, wv.x, acc2[4]); acc2[5] = fma2(a, wv.y, acc2[5]);
            a = pack2(av.w, av.w); acc2[6] = fma2(a, wv.x, acc2[6]); acc2[7] = fma2(a, wv.y, acc2[7]);
        }
        __syncthreads();
    }
    int nb = n0 + (ty << 2);
#pragma unroll
    for (int i = 0; i < 4; i++) {
        int m = m0 + (tx << 2) + i;
        float v[4];
        unpack2(acc2[i*2],   v[0], v[1]);
        unpack2(acc2[i*2+1], v[2], v[3]);
#pragma unroll
        for (int j = 0; j < 4; j++) {
            if (op.Ci)   v[j] += op.Ci[(size_t)m * op.ldci + nb + j];
            if (op.bias) v[j] += op.bias[nb + j];
        }
        float4 o = {v[0], v[1], v[2], v[3]};
        *(float4*)&op.C[(size_t)m * op.ldc + nb] = o;
    }
}

// ---------------------------------------------------------------------------
// precompute helpers
// ---------------------------------------------------------------------------
__global__ void gather_emb_k(const int* __restrict__ inp, const float* __restrict__ tab) {
    int tb = blockIdx.x;
    int idx = inp[tb];
    const float4* src = (const float4*)(tab + (size_t)idx * DW);
    float4* dst = (float4*)(g_emb + (size_t)tb * DW);
    dst[threadIdx.x] = src[threadIdx.x];
}

__global__ void transpose_ctx_k(const float* __restrict__ ctx) {
    int s = blockIdx.x, b = blockIdx.y;
    float4 v = ((const float4*)(ctx + ((size_t)s * DB + b) * DE))[threadIdx.x];
    ((float4*)(g_ctxbse + ((size_t)b * DS + s) * DE))[threadIdx.x] = v;
}

// ---------------------------------------------------------------------------
// persistent decoder
// ---------------------------------------------------------------------------
struct PP {
    const float* mask; const float* Wcopy; const float* bcopy; const float* vatt;
    const float* W_ih0; const float* W_hh0; const float* b_hh0;
    const float* W_ih1; const float* W_hh1; const float* b_ih1; const float* b_hh1;
    const float* W_q;   const float* W_read;
    const float* hidden; const float* init_att;
    float* out;
};

// GRU partial: thread (ks,jj,b) accumulates quarter-k of 6 dots -> red buffer
__device__ __forceinline__ void gru_partial(
    const float* __restrict__ w, float* __restrict__ red,
    int b, int jj, int ks,
    const float* __restrict__ xp, const float* __restrict__ hp)
{
    const float* wxr = w + jj * 512 + ks * 128;
    const float* wxz = wxr + 2048;
    const float* wxn = wxr + 4096;
    const float* whr = w + (12 + jj) * 512 + ks * 128;
    const float* whz = whr + 2048;
    const float* whn = whr + 4096;
    const float* xb = xp + ks * 32 * 256 + b * 4;
    const float* hb = hp + ks * 32 * 256 + b * 4;
    ull ar0=0,ar1=0, az0=0,az1=0, an0=0,an1=0;
    ull hr0=0,hr1=0, hz0=0,hz1=0, hn0=0,hn1=0;
#pragma unroll 4
    for (int k4 = 0; k4 < 32; k4++) {
        ulonglong2 a = *(const ulonglong2*)(xb + k4 * 256);
        ulonglong2 h = *(const ulonglong2*)(hb + k4 * 256);
        ulonglong2 wv;
        wv = *(const ulonglong2*)(wxr + k4 * 4); ar0 = fma2(a.x, wv.x, ar0); ar1 = fma2(a.y, wv.y, ar1);
        wv = *(const ulonglong2*)(wxz + k4 * 4); az0 = fma2(a.x, wv.x, az0); az1 = fma2(a.y, wv.y, az1);
        wv = *(const ulonglong2*)(wxn + k4 * 4); an0 = fma2(a.x, wv.x, an0); an1 = fma2(a.y, wv.y, an1);
        wv = *(const ulonglong2*)(whr + k4 * 4); hr0 = fma2(h.x, wv.x, hr0); hr1 = fma2(h.y, wv.y, hr1);
        wv = *(const ulonglong2*)(whz + k4 * 4); hz0 = fma2(h.x, wv.x, hz0); hz1 = fma2(h.y, wv.y, hz1);
        wv = *(const ulonglong2*)(whn + k4 * 4); hn0 = fma2(h.x, wv.x, hn0); hn1 = fma2(h.y, wv.y, hn1);
    }
    int sub = jj * 64 + b;
    float* r6 = red + (sub * 4 + ks) * 6;
    r6[0] = hsum4(ar0, ar1);
    r6[1] = hsum4(az0, az1);
    r6[2] = hsum4(an0, an1);
    r6[3] = hsum4(hr0, hr1);
    r6[4] = hsum4(hz0, hz1);
    r6[5] = hsum4(hn0, hn1);
}

// gate combine by ks==0 threads (tid<256)
__device__ __forceinline__ void gru_gates(
    const float* __restrict__ red, int tid, int j, int b,
    float bxr, float bxz, float bxn, float bhr, float bhz, float bhn,
    const float* __restrict__ hp, float* __restrict__ hop,
    float* __restrict__ outGH)
{
    const float* r = red + tid * 24;
    float air = bxr + ((r[0] + r[6]) + (r[12] + r[18]));
    float aiz = bxz + ((r[1] + r[7]) + (r[13] + r[19]));
    float ain = bxn + ((r[2] + r[8]) + (r[14] + r[20]));
    float ahr = bhr + ((r[3] + r[9]) + (r[15] + r[21]));
    float ahz = bhz + ((r[4] + r[10]) + (r[16] + r[22]));
    float ahn = bhn + ((r[5] + r[11]) + (r[17] + r[23]));
    float rr = sig_f(air + ahr);
    float zz = sig_f(aiz + ahz);
    float nn = tanh_f(ain + rr * ahn);
    float hprev = hp[pslot(j, b)];
    float hnew  = (1.f - zz) * nn + zz * hprev;
    hop[pslot(j, b)] = hnew;
    outGH[b * 512 + j] = hnew;
}

extern __shared__ float ws[];

__global__ void __launch_bounds__(NTHR, 1) persist_k(PP p) {
    int tid = threadIdx.x, bi = blockIdx.x;
    int b  = tid & 63;
    int jj = (tid >> 6) & 3;
    int ks = tid >> 8;
    float* red = ws + SW_RED;

    // ---- prologue: weight residency + state init ----
    if (bi < 128) {
        int j0 = bi * 4;
        for (int i = tid; i < 24 * 128; i += NTHR) {          // GRU0
            int r = i >> 7, k4 = (i & 127) << 2;
            const float* src = (r < 12)
                ? p.W_ih0 + (size_t)((r >> 2) * 512 + j0 + (r & 3)) * 1024 + 512 + k4
                : p.W_hh0 + (size_t)((((r - 12) >> 2)) * 512 + j0 + ((r - 12) & 3)) * 512 + k4;
            *(float4*)(ws + SW_A + r * 512 + k4) = *(const float4*)src;
        }
        for (int i = tid; i < 24 * 128; i += NTHR) {          // GRU1
            int r = i >> 7, k4 = (i & 127) << 2;
            const float* src = (r < 12)
                ? p.W_ih1 + (size_t)((r >> 2) * 512 + j0 + (r & 3)) * 512 + k4
                : p.W_hh1 + (size_t)((((r - 12) >> 2)) * 512 + j0 + ((r - 12) & 3)) * 512 + k4;
            *(float4*)(ws + SW_C + r * 512 + k4) = *(const float4*)src;
        }
        for (int i = tid; i < 4 * 128; i += NTHR) {           // q rows
            int r = i >> 7, k4 = (i & 127) << 2;
            *(float4*)(ws + SW_Q + r * 512 + k4) =
                *(const float4*)(p.W_q + (size_t)(j0 + r) * 512 + k4);
        }
        for (int i = tid; i < 4 * 128; i += NTHR) {           // roh rows
            int r = i >> 7, k4 = (i & 127) << 2;
            *(float4*)(ws + SW_R1 + r * 512 + k4) =
                *(const float4*)(p.W_read + (size_t)(j0 + r) * G3 + 512 + k4);
        }
    } else if (bi < 144) {
        int c0 = (bi - 128) * 32;
        for (int i = tid; i < 32 * 128; i += NTHR) {          // readout-ctx rows
            int r = i >> 7, k4 = (i & 127) << 2;
            *(float4*)(ws + r * 512 + k4) =
                *(const float4*)(p.W_read + (size_t)(c0 + r) * G3 + 1024 + k4);
        }
    } else {
        for (int i = (bi - 144) * NTHR + tid; i < DB * DH; i += 4 * NTHR) {
            int bb = i >> 9, jx = i & 511;
            int pos = pslot(jx, bb);
            g_h0T[0][pos] = p.hidden[i];
            g_h1T[0][pos] = p.hidden[(size_t)DB*DH + i];
            g_ctxT[pos]   = p.init_att[i];
        }
    }
    gridbar();

    int j = bi * 4 + jj;
    float b0r=0,b0z=0,b0n=0, b1ir=0,b1iz=0,b1in=0, b1hr=0,b1hz=0,b1hn=0;
    if (bi < 128 && tid < 256) {
        b0r  = p.b_hh0[j];  b0z  = p.b_hh0[j + 512];  b0n  = p.b_hh0[j + 1024];
        b1ir = p.b_ih1[j];  b1iz = p.b_ih1[j + 512];  b1in = p.b_ih1[j + 1024];
        b1hr = p.b_hh1[j];  b1hz = p.b_hh1[j + 512];  b1hn = p.b_hh1[j + 1024];
    }
    // tail mapping (blocks 128..143): thread = (col-pair, b)
    int tcp = tid >> 6;               // 0..15
    int tcg = (bi - 128) * 32 + tcp * 2;  // global col
    float ta0 = 0.f, ta1 = 0.f;

    const ull K2    = pack2(2.f*L2E, 2.f*L2E);
    const ull ONE2  = pack2(1.f, 1.f);
    const ull TWO2  = pack2(2.f, 2.f);
    const ull NEG12 = pack2(-1.f, -1.f);

    for (int t = 0; t < DT; t++) {
        int rp = t & 1, wp = rp ^ 1;

        // ---- A: GRU0 || tail-part1(t-1) || copy-gate(t-1) ----
        if (bi < 128) {
            gru_partial(ws + SW_A, red, b, jj, ks, g_ctxT, g_h0T[rp]);
            __syncthreads();
            if (tid < 256) {
                const float* giB = g_gi0e + ((size_t)t * DB + b) * G3;
                gru_gates(red, tid, j, b,
                          giB[j], giB[j + 512], giB[j + 1024], b0r, b0z, b0n,
                          g_h0T[rp], g_h0T[wp],
                          p.out + OFF_GH + ((size_t)t * 2 + 0) * (DB * DH));
            }
        } else if (bi < 144) {
            if (t > 0) {
                ta0 = 0.f; ta1 = 0.f;
                const float* w0 = ws + (tcp * 2) * 512;
                const float* w1 = w0 + 512;
#pragma unroll 4
                for (int e4 = 0; e4 < 64; e4++) {
                    float4 a = *(const float4*)(g_ctxT + e4 * 256 + b * 4);
                    float4 x = *(const float4*)(w0 + e4 * 4);
                    ta0 += a.x*x.x + a.y*x.y + a.z*x.z + a.w*x.w;
                    float4 y = *(const float4*)(w1 + e4 * 4);
                    ta1 += a.x*y.x + a.y*y.y + a.z*y.z + a.w*y.w;
                }
            }
        } else {
            if (t > 0) {
                int gw = (bi - 144) * 32 + (tid >> 5);
                if (gw < 64) {
                    int lane = tid & 31, b2 = gw;
                    const float* h1w = g_h1T[rp];
                    float s = 0.f;
#pragma unroll
                    for (int i = 0; i < 32; i++) {
                        int k = lane + i * 32;
                        float v = (k < 512) ? h1w[pslot(k, b2)] : g_ctxT[pslot(k - 512, b2)];
                        s += v * p.Wcopy[k];
                    }
#pragma unroll
                    for (int o = 16; o; o >>= 1) s += __shfl_down_sync(0xffffffffu, s, o);
                    if (lane == 0)
                        p.out[OFF_CP + (size_t)(t - 1) * DB + b2] = sig_f(s + p.bcopy[0]);
                }
            }
        }
        gridbar();

        // ---- C: GRU1 || tail-part2(t-1) ----
        if (bi < 128) {
            gru_partial(ws + SW_C, red, b, jj, ks, g_h0T[wp], g_h1T[rp]);
            __syncthreads();
            if (tid < 256) {
                gru_gates(red, tid, j, b,
                          b1ir, b1iz, b1in, b1hr, b1hz, b1hn,
                          g_h1T[rp], g_h1T[wp],
                          p.out + OFF_GH + ((size_t)t * 2 + 1) * (DB * DH));
            }
        } else if (bi < 144 && t > 0) {
            const float* w0 = ws + (tcp * 2) * 512;
            const float* w1 = w0 + 512;
#pragma unroll 4
            for (int e4 = 64; e4 < 128; e4++) {
                float4 a = *(const float4*)(g_ctxT + e4 * 256 + b * 4);
                float4 x = *(const float4*)(w0 + e4 * 4);
                ta0 += a.x*x.x + a.y*x.y + a.z*x.z + a.w*x.w;
                float4 y = *(const float4*)(w1 + e4 * 4);
                ta1 += a.x*y.x + a.y*y.y + a.z*y.z + a.w*y.w;
            }
        }
        gridbar();

        // ---- E: q(scaled)+roh (k-split) || tail-write(t-1) ----
        if (bi < 128) {
            const float* h1w = g_h1T[wp] + ks * 32 * 256 + b * 4;
            const float* wq = ws + SW_Q  + jj * 512 + ks * 128;
            const float* wr = ws + SW_R1 + jj * 512 + ks * 128;
            ull q0=0,q1=0, r0=0,r1=0;
#pragma unroll 4
            for (int k4 = 0; k4 < 32; k4++) {
                ulonglong2 a = *(const ulonglong2*)(h1w + k4 * 256);
                ulonglong2 x = *(const ulonglong2*)(wq + k4 * 4);
                q0 = fma2(a.x, x.x, q0); q1 = fma2(a.y, x.y, q1);
                ulonglong2 y = *(const ulonglong2*)(wr + k4 * 4);
                r0 = fma2(a.x, y.x, r0); r1 = fma2(a.y, y.y, r1);
            }
            int sub = jj * 64 + b;
            float* r2v = red + (sub * 4 + ks) * 2;
            r2v[0] = hsum4(q0, q1);
            r2v[1] = hsum4(r0, r1);
            __syncthreads();
            if (tid < 256) {
                const float* rr = red + tid * 8;
                float q = (rr[0] + rr[2]) + (rr[4] + rr[6]);
                float r = (rr[1] + rr[3]) + (rr[5] + rr[7]);
                g_q[b * 512 + j] = q * (2.f * L2E);
                g_roh[t & 1][b * 512 + j] = r;
            }
        } else if (bi < 144 && t > 0) {
            int tt = t - 1;
            const float* re = g_re + ((size_t)tt * DB + b) * DH + tcg;
            const float* rh = g_roh[tt & 1] + (size_t)b * DH + tcg;
            float v0 = ta0 + re[0] + rh[0];
            float v1 = ta1 + re[1] + rh[1];
            p.out[OFF_G + ((size_t)tt * DB + b) * 256 + (tcg >> 1)] = fmaxf(v0, v1);
        }
        gridbar();

        // ---- F1: attention energies (all blocks, warp per (b,s)) ----
        {
            int gw = bi * 32 + (tid >> 5), lane = tid & 31;
            for (int idx = gw; idx < DB * DS; idx += GRIDN * 32) {
                int bb = idx / DS;
                const float* pr = g_pre + (size_t)idx * 512;
                const float* qq = g_q + (size_t)bb * 512;
                ull acc0 = 0, acc1 = 0;
#pragma unroll
                for (int i4 = 0; i4 < 4; i4++) {
                    int a0i = i4 * 128 + lane * 4;
                    ulonglong2 pv = *(const ulonglong2*)(pr + a0i);
                    ulonglong2 qv = *(const ulonglong2*)(qq + a0i);
                    ulonglong2 vv = *(const ulonglong2*)(p.vatt + a0i);
                    acc0 = tanh_acc(pv.x, qv.x, vv.x, acc0, K2, ONE2, TWO2, NEG12);
                    acc1 = tanh_acc(pv.y, qv.y, vv.y, acc1, K2, ONE2, TWO2, NEG12);
                }
                float acc = hsum4(acc0, acc1);
#pragma unroll
                for (int o = 16; o; o >>= 1) acc += __shfl_down_sync(0xffffffffu, acc, o);
                if (lane == 0)
                    g_energy[idx] = (p.mask[idx] > 0.5f) ? -1e18f : acc;
            }
        }
        gridbar();

        // ---- F2: softmax + context (blocks 0..127: 2 blocks per b) ----
        if (bi < 128) {
            int b2 = bi >> 1, half = bi & 1;
            float* es = ws + SW_SC;
            for (int s = tid; s < DS; s += NTHR) es[s] = g_energy[b2 * DS + s];
            __syncthreads();
            if (tid < 32) {
                int lane = tid;
                float m = -3.4e38f;
#pragma unroll
                for (int i = 0; i < 4; i++) { int s = lane + 32 * i; if (s < DS) m = fmaxf(m, es[s]); }
#pragma unroll
                for (int o = 16; o; o >>= 1) m = fmaxf(m, __shfl_xor_sync(0xffffffffu, m, o));
                float pr4[4]; float sum = 0.f;
#pragma unroll
                for (int i = 0; i < 4; i++) {
                    int s = lane + 32 * i;
                    if (s < DS) { pr4[i] = fex2((es[s] - m) * L2E); sum += pr4[i]; }
                }
#pragma unroll
                for (int o = 16; o; o >>= 1) sum += __shfl_xor_sync(0xffffffffu, sum, o);
                float inv = frcp(sum);
#pragma unroll
                for (int i = 0; i < 4; i++) {
                    int s = lane + 32 * i;
                    if (s < DS) {
                        float a = pr4[i] * inv;
                        es[s] = a;
                        if (half == 0) {
                            p.out[OFF_C + ((size_t)t * DB + b2) * DS + s] = a;
                            if (t == DT - 1) p.out[OFF_CL + (size_t)b2 * DS + s] = a;
                        }
                    }
                }
            }
            __syncthreads();
            // ctx: this block covers e in [half*256, half*256+256), s split 4-way
            {
                int e  = half * 256 + (tid & 255);
                int sg = tid >> 8;
                const float* cb = g_ctxbse + (size_t)b2 * DS * DE + e;
                float acc = 0.f;
#pragma unroll 5
                for (int s = sg * 25; s < sg * 25 + 25; s++)
                    acc += es[s] * cb[(size_t)s * DE];
                red[(tid & 255) * 4 + sg] = acc;
            }
            __syncthreads();
            if (tid < 256) {
                const float* rr = red + tid * 4;
                int e = half * 256 + tid;
                g_ctxT[pslot(e, b2)] = (rr[0] + rr[1]) + (rr[2] + rr[3]);
            }
        }
        gridbar();
    }

    // ---- epilogue ----
    if (bi >= 128 && bi < 144) {
        // tail for t=63
        ta0 = 0.f; ta1 = 0.f;
        const float* w0 = ws + (tcp * 2) * 512;
        const float* w1 = w0 + 512;
#pragma unroll 4
        for (int e4 = 0; e4 < 128; e4++) {
            float4 a = *(const float4*)(g_ctxT + e4 * 256 + b * 4);
            float4 x = *(const float4*)(w0 + e4 * 4);
            ta0 += a.x*x.x + a.y*x.y + a.z*x.z + a.w*x.w;
            float4 y = *(const float4*)(w1 + e4 * 4);
            ta1 += a.x*y.x + a.y*y.y + a.z*y.z + a.w*y.w;
        }
        int tt = DT - 1;
        const float* re = g_re + ((size_t)tt * DB + b) * DH + tcg;
        const float* rh = g_roh[tt & 1] + (size_t)b * DH + tcg;
        float v0 = ta0 + re[0] + rh[0];
        float v1 = ta1 + re[1] + rh[1];
        p.out[OFF_G + ((size_t)tt * DB + b) * 256 + (tcg >> 1)] = fmaxf(v0, v1);
    } else if (bi >= 144) {
        // copy gate for t=63 (h1(63) is in buffer 0)
        int gw = (bi - 144) * 32 + (tid >> 5);
        if (gw < 64) {
            int lane = tid & 31, b2 = gw;
            const float* h1w = g_h1T[0];
            float s = 0.f;
#pragma unroll
            for (int i = 0; i < 32; i++) {
                int k = lane + i * 32;
                float v = (k < 512) ? h1w[pslot(k, b2)] : g_ctxT[pslot(k - 512, b2)];
                s += v * p.Wcopy[k];
            }
#pragma unroll
            for (int o = 16; o; o >>= 1) s += __shfl_down_sync(0xffffffffu, s, o);
            if (lane == 0)
                p.out[OFF_CP + (size_t)(DT - 1) * DB + b2] = sig_f(s + p.bcopy[0]);
        }
    } else {
        // finals (step 63 wrote buffer index 0)
        for (int i = bi * NTHR + tid; i < DB * DH; i += 128 * NTHR) {
            int bb = i >> 9, jx = i & 511;
            int pos = pslot(jx, bb);
            p.out[OFF_HF + i]                 = g_h0T[0][pos];
            p.out[OFF_HF + (size_t)DB*DH + i] = g_h1T[0][pos];
            p.out[OFF_CF + i]                 = g_ctxT[pos];
        }
    }
}

// ---------------------------------------------------------------------------
// host
// ---------------------------------------------------------------------------
static GOp mkop(const float* A, int lda, const float* W, int ldw,
                const float* Ci, int ldci, const float* bias,
                float* C, int ldc, int K) {
    GOp o; o.A = A; o.W = W; o.Ci = Ci; o.bias = bias; o.C = C;
    o.lda = lda; o.ldw = ldw; o.ldci = ldci; o.ldc = ldc; o.K = K;
    return o;
}

extern "C" void kernel_launch(void* const* d_in, const int* in_sizes, int n_in,
                              void* d_out, int out_size) {
    (void)in_sizes; (void)n_in; (void)out_size;
    const int*   inp      = (const int*)  d_in[0];
    const float* hidden   = (const float*)d_in[1];
    const float* context  = (const float*)d_in[2];
    const float* mask     = (const float*)d_in[3];
    const float* init_att = (const float*)d_in[4];
    const float* emb_tab  = (const float*)d_in[5];
    const float* W_ih0    = (const float*)d_in[6];
    const float* W_hh0    = (const float*)d_in[7];
    const float* b_ih0    = (const float*)d_in[8];
    const float* b_hh0    = (const float*)d_in[9];
    const float* W_ih1    = (const float*)d_in[10];
    const float* W_hh1    = (const float*)d_in[11];
    const float* b_ih1    = (const float*)d_in[12];
    const float* b_hh1    = (const float*)d_in[13];
    const float* W_pre    = (const float*)d_in[14];
    const float* b_pre    = (const float*)d_in[15];
    const float* W_q      = (const float*)d_in[16];
    const float* v_att    = (const float*)d_in[17];
    const float* W_copy   = (const float*)d_in[18];
    const float* b_copy   = (const float*)d_in[19];
    const float* W_read   = (const float*)d_in[20];
    const float* b_read   = (const float*)d_in[21];
    float* out = (float*)d_out;

    float *p_emb, *p_gi0e, *p_re, *p_pre, *p_ctxbse;
    cudaGetSymbolAddress((void**)&p_emb,    g_emb);
    cudaGetSymbolAddress((void**)&p_gi0e,   g_gi0e);
    cudaGetSymbolAddress((void**)&p_re,     g_re);
    cudaGetSymbolAddress((void**)&p_pre,    g_pre);
    cudaGetSymbolAddress((void**)&p_ctxbse, g_ctxbse);

    cudaFuncSetAttribute(persist_k, cudaFuncAttributeMaxDynamicSharedMemorySize,
                         SW_TOT * sizeof(float));

    gather_emb_k<<<DT*DB, 128>>>(inp, emb_tab);                    // 0
    transpose_ctx_k<<<dim3(DS, DB), 128>>>(context);               // 1

    {
        GOps g; g.op[0] = mkop(p_emb, DW, W_ih0, DW + DE, nullptr, 0, b_ih0, p_gi0e, G3, DW);
        gemm_k<<<dim3(G3/32, (DT*DB)/64, 1), 128>>>(g);            // 2
    }
    {
        GOps g; g.op[0] = mkop(p_emb, DW, W_read, DW + DH + DE, nullptr, 0, b_read, p_re, DH, DW);
        gemm_k<<<dim3(DH/32, (DT*DB)/64, 1), 128>>>(g);            // 3
    }
    {
        GOps g; g.op[0] = mkop(p_ctxbse, DE, W_pre, DE, nullptr, 0, b_pre, p_pre, 512, DE);
        gemm_k<<<dim3(512/32, (DB*DS)/64, 1), 128>>>(g);           // 4
    }

    PP pp;
    pp.mask = mask; pp.Wcopy = W_copy; pp.bcopy = b_copy; pp.vatt = v_att;
    pp.W_ih0 = W_ih0; pp.W_hh0 = W_hh0; pp.b_hh0 = b_hh0;
    pp.W_ih1 = W_ih1; pp.W_hh1 = W_hh1; pp.b_ih1 = b_ih1; pp.b_hh1 = b_hh1;
    pp.W_q = W_q; pp.W_read = W_read;
    pp.hidden = hidden; pp.init_att = init_att;
    pp.out = out;
    persist_k<<<GRIDN, NTHR, SW_TOT * sizeof(float)>>>(pp);        // 5
}